// round 11
// baseline (speedup 1.0000x reference)
#include <cuda_runtime.h>
#include <cuda_bf16.h>
#include <cstdint>

#define Nn  150000
#define Ee  600000
#define FIN 32
#define Hh  128
#define Gg  2048
#define NB_SCAN 586   // ceil(Nn/256)

// ---------------- scratch (device globals) ----------------------------------
__device__ float g_hA [Nn * Hh];
__device__ float g_hB [Nn * Hh];
__device__ float g_pool[Gg * Hh];
__device__ float g_cnt [Gg];
__device__ float g_hd2 [Gg * Hh];
__device__ int   g_deg [Nn];        // also used as fill cursor
__device__ int   g_rowptr[Nn + 1];
__device__ int   g_col [Ee];
__device__ int   g_bsum[1024];
#define WTOT (4096 + 10 * 16384)
__device__ __align__(256) __nv_bfloat16 g_wth[WTOT];
__device__ __align__(256) __nv_bfloat16 g_wtl[WTOT];

// ---------------- helpers -----------------------------------------------------
__device__ __forceinline__ uint32_t smem_u32(const void* p) {
    uint32_t a;
    asm("{ .reg .u64 t; cvta.to.shared.u64 t, %1; cvt.u32.u64 %0, t; }" : "=r"(a) : "l"(p));
    return a;
}

__device__ __forceinline__ void ldsm4(uint32_t (&r)[4], uint32_t addr) {
    asm volatile("ldmatrix.sync.aligned.m8n8.x4.shared.b16 {%0,%1,%2,%3}, [%4];"
                 : "=r"(r[0]), "=r"(r[1]), "=r"(r[2]), "=r"(r[3]) : "r"(addr));
}

__device__ __forceinline__ void mma16816(float (&c)[4], const uint32_t (&a)[4],
                                         uint32_t b0, uint32_t b1) {
    asm volatile(
        "mma.sync.aligned.m16n8k16.row.col.f32.bf16.bf16.f32 "
        "{%0,%1,%2,%3},{%4,%5,%6,%7},{%8,%9},{%0,%1,%2,%3};"
        : "+f"(c[0]), "+f"(c[1]), "+f"(c[2]), "+f"(c[3])
        : "r"(a[0]), "r"(a[1]), "r"(a[2]), "r"(a[3]), "r"(b0), "r"(b1));
}

__device__ __forceinline__ void split2(float a, float b, uint32_t& hv, uint32_t& lv) {
    __nv_bfloat16 ha = __float2bfloat16(a), hb = __float2bfloat16(b);
    float la = a - __bfloat162float(ha), lb = b - __bfloat162float(hb);
    __nv_bfloat162 hp = __halves2bfloat162(ha, hb);
    __nv_bfloat162 lp = __floats2bfloat162_rn(la, lb);
    hv = *reinterpret_cast<uint32_t*>(&hp);
    lv = *reinterpret_cast<uint32_t*>(&lp);
}

__device__ __forceinline__ void red4(float* p, float4 v) {
    asm volatile("red.global.add.v4.f32 [%0], {%1, %2, %3, %4};"
                 :: "l"(p), "f"(v.x), "f"(v.y), "f"(v.z), "f"(v.w) : "memory");
}

// ---------------- smem layout (round-5 proven config) ---------------------------
#define PITCH 136
#define OFF_A_HI 0u
#define OFF_A_LO 17408u
#define OFF_B_HI 34816u
#define OFF_B_LO 69632u
#define SMEM_FUSED 104448

template<int Ks>
__device__ __forceinline__ void gemm_acc(uint32_t sb, float (&acc)[2][4][4],
                                         int lane, int warp_m, int warp_n) {
#pragma unroll
    for (int i = 0; i < 2; i++)
#pragma unroll
        for (int j = 0; j < 4; j++)
#pragma unroll
            for (int k = 0; k < 4; k++) acc[i][j][k] = 0.f;

    int a_r = lane & 15;
    int a_c = (lane & 16) ? 8 : 0;
    int b_r = (lane & 7) + ((lane & 16) ? 8 : 0);
    int b_c = (lane & 8) ? 8 : 0;

#pragma unroll
    for (int kk = 0; kk < Ks / 16; kk++) {
        uint32_t ah[2][4], al[2][4], bh[2][4], bl[2][4];
#pragma unroll
        for (int mt = 0; mt < 2; mt++) {
            uint32_t off = (uint32_t)(((warp_m * 32 + mt * 16 + a_r) * PITCH + kk * 16 + a_c) * 2);
            ldsm4(ah[mt], sb + OFF_A_HI + off);
            ldsm4(al[mt], sb + OFF_A_LO + off);
        }
#pragma unroll
        for (int p = 0; p < 2; p++) {
            uint32_t off = (uint32_t)(((warp_n * 32 + p * 16 + b_r) * PITCH + kk * 16 + b_c) * 2);
            ldsm4(bh[p], sb + OFF_B_HI + off);
            ldsm4(bl[p], sb + OFF_B_LO + off);
        }
#pragma unroll
        for (int mt = 0; mt < 2; mt++)
#pragma unroll
            for (int nt = 0; nt < 4; nt++) {
                int p = nt >> 1, q = (nt & 1) * 2;
                mma16816(acc[mt][nt], ah[mt], bh[p][q], bh[p][q + 1]);
                mma16816(acc[mt][nt], ah[mt], bl[p][q], bl[p][q + 1]);
                mma16816(acc[mt][nt], al[mt], bh[p][q], bh[p][q + 1]);
            }
    }
}

__device__ __forceinline__ void stage_to_smem(char* smem, float (&acc)[2][4][4],
                                              const float* __restrict__ bias,
                                              int lane, int warp_m, int warp_n) {
    int qrow = lane >> 2, qcol = (lane & 3) * 2;
#pragma unroll
    for (int mt = 0; mt < 2; mt++) {
        int r0 = warp_m * 32 + mt * 16 + qrow;
#pragma unroll
        for (int nt = 0; nt < 4; nt++) {
            int col = warp_n * 32 + nt * 8 + qcol;
            float bs0 = __ldg(bias + col), bs1 = __ldg(bias + col + 1);
            float o0 = fmaxf(acc[mt][nt][0] + bs0, 0.f);
            float o1 = fmaxf(acc[mt][nt][1] + bs1, 0.f);
            float o2 = fmaxf(acc[mt][nt][2] + bs0, 0.f);
            float o3 = fmaxf(acc[mt][nt][3] + bs1, 0.f);
            uint32_t h0, l0, h1, l1;
            split2(o0, o1, h0, l0);
            split2(o2, o3, h1, l1);
            *reinterpret_cast<uint32_t*>(smem + OFF_A_HI + ((size_t)r0 * PITCH + col) * 2) = h0;
            *reinterpret_cast<uint32_t*>(smem + OFF_A_LO + ((size_t)r0 * PITCH + col) * 2) = l0;
            *reinterpret_cast<uint32_t*>(smem + OFF_A_HI + ((size_t)(r0 + 8) * PITCH + col) * 2) = h1;
            *reinterpret_cast<uint32_t*>(smem + OFF_A_LO + ((size_t)(r0 + 8) * PITCH + col) * 2) = l1;
        }
    }
}

template<int Kw>
__device__ __forceinline__ void load_w(char* smem, const __nv_bfloat16* __restrict__ wh,
                                       const __nv_bfloat16* __restrict__ wl, int tid) {
    constexpr int CH = Kw / 8;
    constexpr int ITER = 128 * CH / 256;
#pragma unroll
    for (int it = 0; it < ITER; it++) {
        int l = tid + it * 256;
        int row = l / CH, col = (l % CH) * 8;
        *reinterpret_cast<uint4*>(smem + OFF_B_HI + ((size_t)row * PITCH + col) * 2) =
            *reinterpret_cast<const uint4*>(wh + (size_t)row * Kw + col);
        *reinterpret_cast<uint4*>(smem + OFF_B_LO + ((size_t)row * PITCH + col) * 2) =
            *reinterpret_cast<const uint4*>(wl + (size_t)row * Kw + col);
    }
}

struct FusedW {
    const __nv_bfloat16* wh[3];
    const __nv_bfloat16* wl[3];
    const float* b[3];
};

// ---------------- fused gather + MLP ---------------------------------------------
// GATHER: 0 = plain load; 1 = CSR gather(sum A[col]) + self; 2 = load * 1/max(cnt,1).
// ZPOOL: zero pool (Z) + cnt (Zc) inline.
template<int K0, int NST, int GATHER, int ZPOOL>
__global__ __launch_bounds__(256, 2)
void fused_mlp(const float* __restrict__ A,
               const int* __restrict__ rowptr, const int* __restrict__ colv,
               const float* __restrict__ cntp,
               FusedW fw, float* __restrict__ C,
               float* __restrict__ Z, float* __restrict__ Zc, int M) {
    extern __shared__ char smem[];
    uint32_t sb = smem_u32(smem);
    int tid = threadIdx.x, lane = tid & 31, wid = tid >> 5;
    int warp_m = wid & 1, warp_n = wid >> 1;
    int m0 = blockIdx.x * 64;

    // ---- stage A tile (64 x K0) ----
    if (GATHER == 0 || GATHER == 2) {
        constexpr int CH = K0 / 4;
        constexpr int ITER = 64 * CH / 256;
#pragma unroll
        for (int it = 0; it < ITER; it++) {
            int l = tid + it * 256;
            int row = l / CH, col = (l % CH) * 4;
            float4 v = make_float4(0.f, 0.f, 0.f, 0.f);
            int m = m0 + row;
            if (m < M) {
                v = *reinterpret_cast<const float4*>(A + (size_t)m * K0 + col);
                if (GATHER == 2) {
                    float inv = 1.f / fmaxf(__ldg(cntp + m), 1.f);
                    v.x *= inv; v.y *= inv; v.z *= inv; v.w *= inv;
                }
            }
            uint32_t h0, l0, h1, l1;
            split2(v.x, v.y, h0, l0);
            split2(v.z, v.w, h1, l1);
            *reinterpret_cast<uint2*>(smem + OFF_A_HI + ((size_t)row * PITCH + col) * 2) = make_uint2(h0, h1);
            *reinterpret_cast<uint2*>(smem + OFF_A_LO + ((size_t)row * PITCH + col) * 2) = make_uint2(l0, l1);
        }
    } else if (K0 == 128) {
        // warp = 8 consecutive rows; lane = 4-feature chunk; 2-way unrolled gather
#pragma unroll
        for (int i = 0; i < 8; i++) {
            int lrow = wid * 8 + i;
            int row = m0 + lrow;
            float4 acc = make_float4(0.f, 0.f, 0.f, 0.f);
            if (row < M) {
                acc = *reinterpret_cast<const float4*>(A + (size_t)row * 128 + lane * 4);
                int beg = rowptr[row], end = rowptr[row + 1];
                int j = beg;
                for (; j + 2 <= end; j += 2) {
                    int s0 = colv[j], s1 = colv[j + 1];
                    float4 v0 = *reinterpret_cast<const float4*>(A + (size_t)s0 * 128 + lane * 4);
                    float4 v1 = *reinterpret_cast<const float4*>(A + (size_t)s1 * 128 + lane * 4);
                    acc.x += v0.x + v1.x; acc.y += v0.y + v1.y;
                    acc.z += v0.z + v1.z; acc.w += v0.w + v1.w;
                }
                if (j < end) {
                    int s = colv[j];
                    float4 v = *reinterpret_cast<const float4*>(A + (size_t)s * 128 + lane * 4);
                    acc.x += v.x; acc.y += v.y; acc.z += v.z; acc.w += v.w;
                }
            }
            uint32_t h0, l0, h1, l1;
            split2(acc.x, acc.y, h0, l0);
            split2(acc.z, acc.w, h1, l1);
            *reinterpret_cast<uint2*>(smem + OFF_A_HI + ((size_t)lrow * PITCH + lane * 4) * 2) = make_uint2(h0, h1);
            *reinterpret_cast<uint2*>(smem + OFF_A_LO + ((size_t)lrow * PITCH + lane * 4) * 2) = make_uint2(l0, l1);
        }
    } else {
        // K0 == 32: warp covers 4 rows at a time; 2-way unrolled gather
        int sub = lane >> 3, c = (lane & 7) * 4;
#pragma unroll
        for (int i = 0; i < 2; i++) {
            int lrow = wid * 8 + i * 4 + sub;
            int row = m0 + lrow;
            float4 acc = make_float4(0.f, 0.f, 0.f, 0.f);
            if (row < M) {
                acc = *reinterpret_cast<const float4*>(A + (size_t)row * FIN + c);
                int beg = rowptr[row], end = rowptr[row + 1];
                int j = beg;
                for (; j + 2 <= end; j += 2) {
                    int s0 = colv[j], s1 = colv[j + 1];
                    float4 v0 = *reinterpret_cast<const float4*>(A + (size_t)s0 * FIN + c);
                    float4 v1 = *reinterpret_cast<const float4*>(A + (size_t)s1 * FIN + c);
                    acc.x += v0.x + v1.x; acc.y += v0.y + v1.y;
                    acc.z += v0.z + v1.z; acc.w += v0.w + v1.w;
                }
                if (j < end) {
                    int s = colv[j];
                    float4 v = *reinterpret_cast<const float4*>(A + (size_t)s * FIN + c);
                    acc.x += v.x; acc.y += v.y; acc.z += v.z; acc.w += v.w;
                }
            }
            uint32_t h0, l0, h1, l1;
            split2(acc.x, acc.y, h0, l0);
            split2(acc.z, acc.w, h1, l1);
            *reinterpret_cast<uint2*>(smem + OFF_A_HI + ((size_t)lrow * PITCH + c) * 2) = make_uint2(h0, h1);
            *reinterpret_cast<uint2*>(smem + OFF_A_LO + ((size_t)lrow * PITCH + c) * 2) = make_uint2(l0, l1);
        }
    }
    load_w<K0>(smem, fw.wh[0], fw.wl[0], tid);
    __syncthreads();

    if (ZPOOL) {
        const float4 z4 = make_float4(0.f, 0.f, 0.f, 0.f);
        if (blockIdx.x < 32) {
#pragma unroll
            for (int it = 0; it < 8; it++) {
                int i = tid + it * 256;
                int row = (int)blockIdx.x * 64 + (i >> 5);
                reinterpret_cast<float4*>(Z + (size_t)row * 128)[i & 31] = z4;
            }
        } else if (blockIdx.x == 32) {
#pragma unroll
            for (int it = 0; it < 2; it++)
                reinterpret_cast<float4*>(Zc)[tid + it * 256] = z4;
        }
    }

    float acc[2][4][4];
    gemm_acc<K0>(sb, acc, lane, warp_m, warp_n);

#pragma unroll
    for (int s = 1; s < NST; s++) {
        __syncthreads();
        stage_to_smem(smem, acc, fw.b[s - 1], lane, warp_m, warp_n);
        load_w<128>(smem, fw.wh[s], fw.wl[s], tid);
        __syncthreads();
        gemm_acc<128>(sb, acc, lane, warp_m, warp_n);
    }

    const float* bias = fw.b[NST - 1];
    int qrow = lane >> 2, qcol = (lane & 3) * 2;
#pragma unroll
    for (int mt = 0; mt < 2; mt++) {
        int r0 = m0 + warp_m * 32 + mt * 16 + qrow;
        int r1 = r0 + 8;
#pragma unroll
        for (int nt = 0; nt < 4; nt++) {
            int col = warp_n * 32 + nt * 8 + qcol;
            float bs0 = __ldg(bias + col), bs1 = __ldg(bias + col + 1);
            float o0 = fmaxf(acc[mt][nt][0] + bs0, 0.f);
            float o1 = fmaxf(acc[mt][nt][1] + bs1, 0.f);
            float o2 = fmaxf(acc[mt][nt][2] + bs0, 0.f);
            float o3 = fmaxf(acc[mt][nt][3] + bs1, 0.f);
            if (r0 < M) *reinterpret_cast<float2*>(C + (size_t)r0 * 128 + col) = make_float2(o0, o1);
            if (r1 < M) *reinterpret_cast<float2*>(C + (size_t)r1 * 128 + col) = make_float2(o2, o3);
        }
    }
}

// ---------------- weight prep (11 slots) + deg zero, one launch -----------------
struct WP { const float* p[11]; };
#define PREP_WBLOCKS (11 * 128)
#define PREP_ZBLOCKS ((Nn + 127) / 128)

__global__ void prep_all(WP wp, __nv_bfloat16* __restrict__ hi, __nv_bfloat16* __restrict__ lo,
                         int* __restrict__ deg) {
    if (blockIdx.x >= PREP_WBLOCKS) {
        int i = (blockIdx.x - PREP_WBLOCKS) * 128 + threadIdx.x;
        if (i < Nn) deg[i] = 0;
        return;
    }
    int slot = blockIdx.x >> 7;
    int n = blockIdx.x & 127;
    int K = (slot == 0) ? FIN : Hh;
    size_t off = (slot == 0) ? 0 : (size_t)4096 + (size_t)(slot - 1) * 16384;
    const float* W = wp.p[slot];
    for (int k = threadIdx.x; k < K; k += blockDim.x) {
        float v = W[k * Hh + n];
        __nv_bfloat16 h = __float2bfloat16(v);
        hi[off + (size_t)n * K + k] = h;
        lo[off + (size_t)n * K + k] = __float2bfloat16(v - __bfloat162float(h));
    }
}

// ---------------- CSR build -----------------------------------------------------
__global__ void deg_k(const int* __restrict__ ei, int* __restrict__ deg) {
    int e = blockIdx.x * blockDim.x + threadIdx.x;
    if (e < Ee) atomicAdd(&deg[ei[Ee + e]], 1);
}

__global__ void scan1(const int* __restrict__ deg, int* __restrict__ bsum) {
    __shared__ int sm[256];
    int i = blockIdx.x * 256 + threadIdx.x;
    sm[threadIdx.x] = (i < Nn) ? deg[i] : 0;
    __syncthreads();
    for (int s = 128; s > 0; s >>= 1) {
        if (threadIdx.x < s) sm[threadIdx.x] += sm[threadIdx.x + s];
        __syncthreads();
    }
    if (threadIdx.x == 0) bsum[blockIdx.x] = sm[0];
}

__global__ void scan2(int* __restrict__ bsum) {
    __shared__ int sm[1024];
    int t = threadIdx.x;
    sm[t] = (t < NB_SCAN) ? bsum[t] : 0;
    __syncthreads();
    for (int s = 1; s < 1024; s <<= 1) {
        int v = (t >= s) ? sm[t - s] : 0;
        __syncthreads();
        sm[t] += v;
        __syncthreads();
    }
    if (t < NB_SCAN) bsum[t] = sm[t];   // inclusive per-block sums
}

__global__ void scan3(const int* __restrict__ deg, const int* __restrict__ bsum,
                      int* __restrict__ rowptr, int* __restrict__ cursor) {
    __shared__ int sm[256];
    int i = blockIdx.x * 256 + threadIdx.x;
    int v = (i < Nn) ? deg[i] : 0;
    sm[threadIdx.x] = v;
    __syncthreads();
    for (int s = 1; s < 256; s <<= 1) {
        int u = (threadIdx.x >= s) ? sm[threadIdx.x - s] : 0;
        __syncthreads();
        sm[threadIdx.x] += u;
        __syncthreads();
    }
    int excl = sm[threadIdx.x] - v;
    int base = (blockIdx.x > 0) ? bsum[blockIdx.x - 1] : 0;
    if (i < Nn) {
        rowptr[i] = base + excl;
        cursor[i] = base + excl;
    }
    if (i == 0) rowptr[Nn] = Ee;
}

__global__ void fill_k(const int* __restrict__ ei, int* __restrict__ cursor,
                       int* __restrict__ col) {
    int e = blockIdx.x * blockDim.x + threadIdx.x;
    if (e >= Ee) return;
    int d = ei[Ee + e];
    int p = atomicAdd(&cursor[d], 1);
    col[p] = ei[e];
}

// ---------------- pooling (sum + count fused) / head ------------------------------
#define PR 16
__global__ void pool_k(const float* __restrict__ h, const int* __restrict__ batch,
                       float* __restrict__ pool, float* __restrict__ cnt) {
    int gw = (blockIdx.x * blockDim.x + threadIdx.x) >> 5;
    int lane = threadIdx.x & 31;
    const int NB = (Nn + PR - 1) / PR;
    if (gw >= NB) return;
    int n0 = gw * PR;
    int n1 = n0 + PR < Nn ? n0 + PR : Nn;
    float4 acc = make_float4(0.f, 0.f, 0.f, 0.f);
    float cacc = 0.f;
    int cur = batch[n0];
    for (int n = n0; n < n1; n++) {
        int g = batch[n];
        if (g != cur) {
            red4(&pool[(size_t)cur * Hh + lane * 4], acc);
            if (lane == 0) atomicAdd(&cnt[cur], cacc);
            acc = make_float4(0.f, 0.f, 0.f, 0.f);
            cacc = 0.f;
            cur = g;
        }
        float4 v = *reinterpret_cast<const float4*>(h + (size_t)n * Hh + lane * 4);
        acc.x += v.x; acc.y += v.y; acc.z += v.z; acc.w += v.w;
        cacc += 1.f;
    }
    red4(&pool[(size_t)cur * Hh + lane * 4], acc);
    if (lane == 0) atomicAdd(&cnt[cur], cacc);
}

__global__ void out_k(const float* __restrict__ g2, const float* __restrict__ ow,
                      const float* __restrict__ ob, float* __restrict__ out) {
    int g = blockIdx.x * blockDim.x + threadIdx.x;
    if (g >= Gg) return;
    float s0 = ob[0], s1 = ob[1];
#pragma unroll 4
    for (int k = 0; k < Hh; k++) {
        float v = g2[g * Hh + k];
        s0 += v * ow[k * 2 + 0];
        s1 += v * ow[k * 2 + 1];
    }
    out[g * 2 + 0] = s0;
    out[g * 2 + 1] = s1;
}

// ---------------- launch ----------------------------------------------------------
extern "C" void kernel_launch(void* const* d_in, const int* in_sizes, int n_in,
                              void* d_out, int out_size) {
    const float* x     = (const float*)d_in[0];
    const int*   ei    = (const int*)  d_in[1];
    const int*   batch = (const int*)  d_in[2];
    const float* b1[3], *b2[3], *b3[3];
    WP wp;
    for (int L = 0; L < 3; L++) {
        wp.p[3 * L + 0] = (const float*)d_in[3 + 6 * L + 0];
        b1[L]           = (const float*)d_in[3 + 6 * L + 1];
        wp.p[3 * L + 1] = (const float*)d_in[3 + 6 * L + 2];
        b2[L]           = (const float*)d_in[3 + 6 * L + 3];
        wp.p[3 * L + 2] = (const float*)d_in[3 + 6 * L + 4];
        b3[L]           = (const float*)d_in[3 + 6 * L + 5];
    }
    wp.p[9]  = (const float*)d_in[21];
    const float* fc0b = (const float*)d_in[22];
    wp.p[10] = (const float*)d_in[23];
    const float* fc1b = (const float*)d_in[24];
    const float* outw = (const float*)d_in[25];
    const float* outb = (const float*)d_in[26];

    float *hA, *hB, *pool, *cnt, *hd2;
    int *deg, *rowptr, *colv, *bsum;
    __nv_bfloat16 *wth, *wtl;
    cudaGetSymbolAddress((void**)&hA,     g_hA);
    cudaGetSymbolAddress((void**)&hB,     g_hB);
    cudaGetSymbolAddress((void**)&pool,   g_pool);
    cudaGetSymbolAddress((void**)&cnt,    g_cnt);
    cudaGetSymbolAddress((void**)&hd2,    g_hd2);
    cudaGetSymbolAddress((void**)&deg,    g_deg);
    cudaGetSymbolAddress((void**)&rowptr, g_rowptr);
    cudaGetSymbolAddress((void**)&colv,   g_col);
    cudaGetSymbolAddress((void**)&bsum,   g_bsum);
    cudaGetSymbolAddress((void**)&wth,    g_wth);
    cudaGetSymbolAddress((void**)&wtl,    g_wtl);

    auto woff = [](int s) -> size_t { return s == 0 ? 0 : (size_t)4096 + (size_t)(s - 1) * 16384; };

    cudaFuncSetAttribute(fused_mlp<FIN, 3, 1, 0>, cudaFuncAttributeMaxDynamicSharedMemorySize, SMEM_FUSED);
    cudaFuncSetAttribute(fused_mlp<Hh, 3, 1, 0>,  cudaFuncAttributeMaxDynamicSharedMemorySize, SMEM_FUSED);
    cudaFuncSetAttribute(fused_mlp<Hh, 3, 1, 1>,  cudaFuncAttributeMaxDynamicSharedMemorySize, SMEM_FUSED);
    cudaFuncSetAttribute(fused_mlp<Hh, 2, 2, 0>,  cudaFuncAttributeMaxDynamicSharedMemorySize, SMEM_FUSED);

    const int TB = 256;
    int ggrid = (Nn + 63) / 64;   // 2344
    int hgrid = (Gg + 63) / 64;   // 32

    // ---- weight prep + deg zero (one launch) + CSR build ----
    prep_all<<<PREP_WBLOCKS + PREP_ZBLOCKS, 128>>>(wp, wth, wtl, deg);
    deg_k<<<(Ee + TB - 1) / TB, TB>>>(ei, deg);
    scan1<<<NB_SCAN, 256>>>(deg, bsum);
    scan2<<<1, 1024>>>(bsum);
    scan3<<<NB_SCAN, 256>>>(deg, bsum, rowptr, deg);
    fill_k<<<(Ee + TB - 1) / TB, TB>>>(ei, deg, colv);

    // ---- layer 0: gather(x) + MLP -> hA ----
    {
        FusedW fw;
        for (int s = 0; s < 3; s++) { fw.wh[s] = wth + woff(s); fw.wl[s] = wtl + woff(s); }
        fw.b[0] = b1[0]; fw.b[1] = b2[0]; fw.b[2] = b3[0];
        fused_mlp<FIN, 3, 1, 0><<<ggrid, 256, SMEM_FUSED>>>(x, rowptr, colv, nullptr, fw, hA,
                                                            nullptr, nullptr, Nn);
    }
    // ---- layer 1: gather(hA) + MLP -> hB ----
    {
        FusedW fw;
        for (int s = 0; s < 3; s++) { fw.wh[s] = wth + woff(3 + s); fw.wl[s] = wtl + woff(3 + s); }
        fw.b[0] = b1[1]; fw.b[1] = b2[1]; fw.b[2] = b3[1];
        fused_mlp<Hh, 3, 1, 0><<<ggrid, 256, SMEM_FUSED>>>(hA, rowptr, colv, nullptr, fw, hB,
                                                           nullptr, nullptr, Nn);
    }
    // ---- layer 2: gather(hB) + MLP -> hA (zeroes pool + cnt inline) ----
    {
        FusedW fw;
        for (int s = 0; s < 3; s++) { fw.wh[s] = wth + woff(6 + s); fw.wl[s] = wtl + woff(6 + s); }
        fw.b[0] = b1[2]; fw.b[1] = b2[2]; fw.b[2] = b3[2];
        fused_mlp<Hh, 3, 1, 1><<<ggrid, 256, SMEM_FUSED>>>(hB, rowptr, colv, nullptr, fw, hA,
                                                           pool, cnt, Nn);
    }

    // ---- global mean pool (sum + count in one kernel) ----
    {
        int warps = (Nn + PR - 1) / PR;
        pool_k<<<(warps * 32 + TB - 1) / TB, TB>>>(hA, batch, pool, cnt);
    }

    // ---- classifier head (fc0 + fc1 fused; /count folded into A-load) ----
    {
        FusedW fw;
        fw.wh[0] = wth + woff(9);  fw.wl[0] = wtl + woff(9);
        fw.wh[1] = wth + woff(10); fw.wl[1] = wtl + woff(10);
        fw.wh[2] = nullptr;        fw.wl[2] = nullptr;
        fw.b[0] = fc0b; fw.b[1] = fc1b; fw.b[2] = nullptr;
        fused_mlp<Hh, 2, 2, 0><<<hgrid, 256, SMEM_FUSED>>>(pool, nullptr, nullptr, cnt, fw, hd2,
                                                           nullptr, nullptr, Gg);
    }
    out_k<<<(Gg + 127) / 128, 128>>>(hd2, outw, outb, (float*)d_out);
}

// round 12
// speedup vs baseline: 1.0407x; 1.0407x over previous
#include <cuda_runtime.h>
#include <cuda_bf16.h>
#include <cstdint>

#define Nn  150000
#define Ee  600000
#define FIN 32
#define Hh  128
#define Gg  2048
#define NB_SCAN 586   // ceil(Nn/256)

// ---------------- scratch (device globals) ----------------------------------
__device__ float g_hA [Nn * Hh];
__device__ float g_hB [Nn * Hh];
__device__ float g_pool[Gg * Hh];
__device__ float g_cnt [Gg];
__device__ float g_hd2 [Gg * Hh];
__device__ int   g_deg [Nn];        // also used as fill cursor
__device__ int   g_rowptr[Nn + 1];
__device__ int   g_col [Ee];
__device__ int   g_bsum[1024];
#define WTOT (4096 + 10 * 16384)
__device__ __align__(256) __nv_bfloat16 g_wth[WTOT];
__device__ __align__(256) __nv_bfloat16 g_wtl[WTOT];

// ---------------- helpers -----------------------------------------------------
__device__ __forceinline__ uint32_t smem_u32(const void* p) {
    uint32_t a;
    asm("{ .reg .u64 t; cvta.to.shared.u64 t, %1; cvt.u32.u64 %0, t; }" : "=r"(a) : "l"(p));
    return a;
}

__device__ __forceinline__ void ldsm4(uint32_t (&r)[4], uint32_t addr) {
    asm volatile("ldmatrix.sync.aligned.m8n8.x4.shared.b16 {%0,%1,%2,%3}, [%4];"
                 : "=r"(r[0]), "=r"(r[1]), "=r"(r[2]), "=r"(r[3]) : "r"(addr));
}

__device__ __forceinline__ void mma16816(float (&c)[4], const uint32_t (&a)[4],
                                         uint32_t b0, uint32_t b1) {
    asm volatile(
        "mma.sync.aligned.m16n8k16.row.col.f32.bf16.bf16.f32 "
        "{%0,%1,%2,%3},{%4,%5,%6,%7},{%8,%9},{%0,%1,%2,%3};"
        : "+f"(c[0]), "+f"(c[1]), "+f"(c[2]), "+f"(c[3])
        : "r"(a[0]), "r"(a[1]), "r"(a[2]), "r"(a[3]), "r"(b0), "r"(b1));
}

__device__ __forceinline__ void split2(float a, float b, uint32_t& hv, uint32_t& lv) {
    __nv_bfloat16 ha = __float2bfloat16(a), hb = __float2bfloat16(b);
    float la = a - __bfloat162float(ha), lb = b - __bfloat162float(hb);
    __nv_bfloat162 hp = __halves2bfloat162(ha, hb);
    __nv_bfloat162 lp = __floats2bfloat162_rn(la, lb);
    hv = *reinterpret_cast<uint32_t*>(&hp);
    lv = *reinterpret_cast<uint32_t*>(&lp);
}

__device__ __forceinline__ void red4(float* p, float4 v) {
    asm volatile("red.global.add.v4.f32 [%0], {%1, %2, %3, %4};"
                 :: "l"(p), "f"(v.x), "f"(v.y), "f"(v.z), "f"(v.w) : "memory");
}

// ---------------- smem layout (round-5 proven config) ---------------------------
#define PITCH 136
#define OFF_A_HI 0u
#define OFF_A_LO 17408u
#define OFF_B_HI 34816u
#define OFF_B_LO 69632u
#define SMEM_FUSED 104448

template<int Ks>
__device__ __forceinline__ void gemm_acc(uint32_t sb, float (&acc)[2][4][4],
                                         int lane, int warp_m, int warp_n) {
#pragma unroll
    for (int i = 0; i < 2; i++)
#pragma unroll
        for (int j = 0; j < 4; j++)
#pragma unroll
            for (int k = 0; k < 4; k++) acc[i][j][k] = 0.f;

    int a_r = lane & 15;
    int a_c = (lane & 16) ? 8 : 0;
    int b_r = (lane & 7) + ((lane & 16) ? 8 : 0);
    int b_c = (lane & 8) ? 8 : 0;

#pragma unroll
    for (int kk = 0; kk < Ks / 16; kk++) {
        uint32_t ah[2][4], al[2][4], bh[2][4], bl[2][4];
#pragma unroll
        for (int mt = 0; mt < 2; mt++) {
            uint32_t off = (uint32_t)(((warp_m * 32 + mt * 16 + a_r) * PITCH + kk * 16 + a_c) * 2);
            ldsm4(ah[mt], sb + OFF_A_HI + off);
            ldsm4(al[mt], sb + OFF_A_LO + off);
        }
#pragma unroll
        for (int p = 0; p < 2; p++) {
            uint32_t off = (uint32_t)(((warp_n * 32 + p * 16 + b_r) * PITCH + kk * 16 + b_c) * 2);
            ldsm4(bh[p], sb + OFF_B_HI + off);
            ldsm4(bl[p], sb + OFF_B_LO + off);
        }
#pragma unroll
        for (int mt = 0; mt < 2; mt++)
#pragma unroll
            for (int nt = 0; nt < 4; nt++) {
                int p = nt >> 1, q = (nt & 1) * 2;
                mma16816(acc[mt][nt], ah[mt], bh[p][q], bh[p][q + 1]);
                mma16816(acc[mt][nt], ah[mt], bl[p][q], bl[p][q + 1]);
                mma16816(acc[mt][nt], al[mt], bh[p][q], bh[p][q + 1]);
            }
    }
}

__device__ __forceinline__ void stage_to_smem(char* smem, float (&acc)[2][4][4],
                                              const float* __restrict__ bias,
                                              int lane, int warp_m, int warp_n) {
    int qrow = lane >> 2, qcol = (lane & 3) * 2;
#pragma unroll
    for (int mt = 0; mt < 2; mt++) {
        int r0 = warp_m * 32 + mt * 16 + qrow;
#pragma unroll
        for (int nt = 0; nt < 4; nt++) {
            int col = warp_n * 32 + nt * 8 + qcol;
            float bs0 = __ldg(bias + col), bs1 = __ldg(bias + col + 1);
            float o0 = fmaxf(acc[mt][nt][0] + bs0, 0.f);
            float o1 = fmaxf(acc[mt][nt][1] + bs1, 0.f);
            float o2 = fmaxf(acc[mt][nt][2] + bs0, 0.f);
            float o3 = fmaxf(acc[mt][nt][3] + bs1, 0.f);
            uint32_t h0, l0, h1, l1;
            split2(o0, o1, h0, l0);
            split2(o2, o3, h1, l1);
            *reinterpret_cast<uint32_t*>(smem + OFF_A_HI + ((size_t)r0 * PITCH + col) * 2) = h0;
            *reinterpret_cast<uint32_t*>(smem + OFF_A_LO + ((size_t)r0 * PITCH + col) * 2) = l0;
            *reinterpret_cast<uint32_t*>(smem + OFF_A_HI + ((size_t)(r0 + 8) * PITCH + col) * 2) = h1;
            *reinterpret_cast<uint32_t*>(smem + OFF_A_LO + ((size_t)(r0 + 8) * PITCH + col) * 2) = l1;
        }
    }
}

template<int Kw>
__device__ __forceinline__ void load_w(char* smem, const __nv_bfloat16* __restrict__ wh,
                                       const __nv_bfloat16* __restrict__ wl, int tid) {
    constexpr int CH = Kw / 8;
    constexpr int ITER = 128 * CH / 256;
#pragma unroll
    for (int it = 0; it < ITER; it++) {
        int l = tid + it * 256;
        int row = l / CH, col = (l % CH) * 8;
        *reinterpret_cast<uint4*>(smem + OFF_B_HI + ((size_t)row * PITCH + col) * 2) =
            *reinterpret_cast<const uint4*>(wh + (size_t)row * Kw + col);
        *reinterpret_cast<uint4*>(smem + OFF_B_LO + ((size_t)row * PITCH + col) * 2) =
            *reinterpret_cast<const uint4*>(wl + (size_t)row * Kw + col);
    }
}

struct FusedW {
    const __nv_bfloat16* wh[3];
    const __nv_bfloat16* wl[3];
    const float* b[3];
};

// ---------------- fused gather + MLP ---------------------------------------------
// GATHER: 0 = plain load; 1 = CSR gather(sum A[col]) + self (serial loop — round-10
//         register footprint, 2-way unroll regressed in round 11); 2 = load * 1/max(cnt,1).
// ZPOOL: zero pool (Z) + cnt (Zc) inline.
template<int K0, int NST, int GATHER, int ZPOOL>
__global__ __launch_bounds__(256, 2)
void fused_mlp(const float* __restrict__ A,
               const int* __restrict__ rowptr, const int* __restrict__ colv,
               const float* __restrict__ cntp,
               FusedW fw, float* __restrict__ C,
               float* __restrict__ Z, float* __restrict__ Zc, int M) {
    extern __shared__ char smem[];
    uint32_t sb = smem_u32(smem);
    int tid = threadIdx.x, lane = tid & 31, wid = tid >> 5;
    int warp_m = wid & 1, warp_n = wid >> 1;
    int m0 = blockIdx.x * 64;

    // ---- stage A tile (64 x K0) ----
    if (GATHER == 0 || GATHER == 2) {
        constexpr int CH = K0 / 4;
        constexpr int ITER = 64 * CH / 256;
#pragma unroll
        for (int it = 0; it < ITER; it++) {
            int l = tid + it * 256;
            int row = l / CH, col = (l % CH) * 4;
            float4 v = make_float4(0.f, 0.f, 0.f, 0.f);
            int m = m0 + row;
            if (m < M) {
                v = *reinterpret_cast<const float4*>(A + (size_t)m * K0 + col);
                if (GATHER == 2) {
                    float inv = 1.f / fmaxf(__ldg(cntp + m), 1.f);
                    v.x *= inv; v.y *= inv; v.z *= inv; v.w *= inv;
                }
            }
            uint32_t h0, l0, h1, l1;
            split2(v.x, v.y, h0, l0);
            split2(v.z, v.w, h1, l1);
            *reinterpret_cast<uint2*>(smem + OFF_A_HI + ((size_t)row * PITCH + col) * 2) = make_uint2(h0, h1);
            *reinterpret_cast<uint2*>(smem + OFF_A_LO + ((size_t)row * PITCH + col) * 2) = make_uint2(l0, l1);
        }
    } else if (K0 == 128) {
        // warp = 8 consecutive rows; lane = 4-feature chunk (serial neighbor loop)
#pragma unroll
        for (int i = 0; i < 8; i++) {
            int lrow = wid * 8 + i;
            int row = m0 + lrow;
            float4 acc = make_float4(0.f, 0.f, 0.f, 0.f);
            if (row < M) {
                acc = *reinterpret_cast<const float4*>(A + (size_t)row * 128 + lane * 4);
                int beg = rowptr[row], end = rowptr[row + 1];
                for (int j = beg; j < end; j++) {
                    int s = colv[j];
                    float4 v = *reinterpret_cast<const float4*>(A + (size_t)s * 128 + lane * 4);
                    acc.x += v.x; acc.y += v.y; acc.z += v.z; acc.w += v.w;
                }
            }
            uint32_t h0, l0, h1, l1;
            split2(acc.x, acc.y, h0, l0);
            split2(acc.z, acc.w, h1, l1);
            *reinterpret_cast<uint2*>(smem + OFF_A_HI + ((size_t)lrow * PITCH + lane * 4) * 2) = make_uint2(h0, h1);
            *reinterpret_cast<uint2*>(smem + OFF_A_LO + ((size_t)lrow * PITCH + lane * 4) * 2) = make_uint2(l0, l1);
        }
    } else {
        // K0 == 32: warp covers 4 rows at a time (serial neighbor loop)
        int sub = lane >> 3, c = (lane & 7) * 4;
#pragma unroll
        for (int i = 0; i < 2; i++) {
            int lrow = wid * 8 + i * 4 + sub;
            int row = m0 + lrow;
            float4 acc = make_float4(0.f, 0.f, 0.f, 0.f);
            if (row < M) {
                acc = *reinterpret_cast<const float4*>(A + (size_t)row * FIN + c);
                int beg = rowptr[row], end = rowptr[row + 1];
                for (int j = beg; j < end; j++) {
                    int s = colv[j];
                    float4 v = *reinterpret_cast<const float4*>(A + (size_t)s * FIN + c);
                    acc.x += v.x; acc.y += v.y; acc.z += v.z; acc.w += v.w;
                }
            }
            uint32_t h0, l0, h1, l1;
            split2(acc.x, acc.y, h0, l0);
            split2(acc.z, acc.w, h1, l1);
            *reinterpret_cast<uint2*>(smem + OFF_A_HI + ((size_t)lrow * PITCH + c) * 2) = make_uint2(h0, h1);
            *reinterpret_cast<uint2*>(smem + OFF_A_LO + ((size_t)lrow * PITCH + c) * 2) = make_uint2(l0, l1);
        }
    }
    load_w<K0>(smem, fw.wh[0], fw.wl[0], tid);
    __syncthreads();

    if (ZPOOL) {
        const float4 z4 = make_float4(0.f, 0.f, 0.f, 0.f);
        if (blockIdx.x < 32) {
#pragma unroll
            for (int it = 0; it < 8; it++) {
                int i = tid + it * 256;
                int row = (int)blockIdx.x * 64 + (i >> 5);
                reinterpret_cast<float4*>(Z + (size_t)row * 128)[i & 31] = z4;
            }
        } else if (blockIdx.x == 32) {
#pragma unroll
            for (int it = 0; it < 2; it++)
                reinterpret_cast<float4*>(Zc)[tid + it * 256] = z4;
        }
    }

    float acc[2][4][4];
    gemm_acc<K0>(sb, acc, lane, warp_m, warp_n);

#pragma unroll
    for (int s = 1; s < NST; s++) {
        __syncthreads();
        stage_to_smem(smem, acc, fw.b[s - 1], lane, warp_m, warp_n);
        load_w<128>(smem, fw.wh[s], fw.wl[s], tid);
        __syncthreads();
        gemm_acc<128>(sb, acc, lane, warp_m, warp_n);
    }

    const float* bias = fw.b[NST - 1];
    int qrow = lane >> 2, qcol = (lane & 3) * 2;
#pragma unroll
    for (int mt = 0; mt < 2; mt++) {
        int r0 = m0 + warp_m * 32 + mt * 16 + qrow;
        int r1 = r0 + 8;
#pragma unroll
        for (int nt = 0; nt < 4; nt++) {
            int col = warp_n * 32 + nt * 8 + qcol;
            float bs0 = __ldg(bias + col), bs1 = __ldg(bias + col + 1);
            float o0 = fmaxf(acc[mt][nt][0] + bs0, 0.f);
            float o1 = fmaxf(acc[mt][nt][1] + bs1, 0.f);
            float o2 = fmaxf(acc[mt][nt][2] + bs0, 0.f);
            float o3 = fmaxf(acc[mt][nt][3] + bs1, 0.f);
            if (r0 < M) *reinterpret_cast<float2*>(C + (size_t)r0 * 128 + col) = make_float2(o0, o1);
            if (r1 < M) *reinterpret_cast<float2*>(C + (size_t)r1 * 128 + col) = make_float2(o2, o3);
        }
    }
}

// ---------------- weight prep (11 slots) + deg zero, one launch -----------------
struct WP { const float* p[11]; };
#define PREP_WBLOCKS (11 * 128)
#define PREP_ZBLOCKS ((Nn + 127) / 128)

__global__ void prep_all(WP wp, __nv_bfloat16* __restrict__ hi, __nv_bfloat16* __restrict__ lo,
                         int* __restrict__ deg) {
    if (blockIdx.x >= PREP_WBLOCKS) {
        int i = (blockIdx.x - PREP_WBLOCKS) * 128 + threadIdx.x;
        if (i < Nn) deg[i] = 0;
        return;
    }
    int slot = blockIdx.x >> 7;
    int n = blockIdx.x & 127;
    int K = (slot == 0) ? FIN : Hh;
    size_t off = (slot == 0) ? 0 : (size_t)4096 + (size_t)(slot - 1) * 16384;
    const float* W = wp.p[slot];
    for (int k = threadIdx.x; k < K; k += blockDim.x) {
        float v = W[k * Hh + n];
        __nv_bfloat16 h = __float2bfloat16(v);
        hi[off + (size_t)n * K + k] = h;
        lo[off + (size_t)n * K + k] = __float2bfloat16(v - __bfloat162float(h));
    }
}

// ---------------- CSR build -----------------------------------------------------
__global__ void deg_k(const int* __restrict__ ei, int* __restrict__ deg) {
    int e = blockIdx.x * blockDim.x + threadIdx.x;
    if (e < Ee) atomicAdd(&deg[ei[Ee + e]], 1);
}

__global__ void scan1(const int* __restrict__ deg, int* __restrict__ bsum) {
    __shared__ int sm[256];
    int i = blockIdx.x * 256 + threadIdx.x;
    sm[threadIdx.x] = (i < Nn) ? deg[i] : 0;
    __syncthreads();
    for (int s = 128; s > 0; s >>= 1) {
        if (threadIdx.x < s) sm[threadIdx.x] += sm[threadIdx.x + s];
        __syncthreads();
    }
    if (threadIdx.x == 0) bsum[blockIdx.x] = sm[0];
}

__global__ void scan2(int* __restrict__ bsum) {
    __shared__ int sm[1024];
    int t = threadIdx.x;
    sm[t] = (t < NB_SCAN) ? bsum[t] : 0;
    __syncthreads();
    for (int s = 1; s < 1024; s <<= 1) {
        int v = (t >= s) ? sm[t - s] : 0;
        __syncthreads();
        sm[t] += v;
        __syncthreads();
    }
    if (t < NB_SCAN) bsum[t] = sm[t];   // inclusive per-block sums
}

__global__ void scan3(const int* __restrict__ deg, const int* __restrict__ bsum,
                      int* __restrict__ rowptr, int* __restrict__ cursor) {
    __shared__ int sm[256];
    int i = blockIdx.x * 256 + threadIdx.x;
    int v = (i < Nn) ? deg[i] : 0;
    sm[threadIdx.x] = v;
    __syncthreads();
    for (int s = 1; s < 256; s <<= 1) {
        int u = (threadIdx.x >= s) ? sm[threadIdx.x - s] : 0;
        __syncthreads();
        sm[threadIdx.x] += u;
        __syncthreads();
    }
    int excl = sm[threadIdx.x] - v;
    int base = (blockIdx.x > 0) ? bsum[blockIdx.x - 1] : 0;
    if (i < Nn) {
        rowptr[i] = base + excl;
        cursor[i] = base + excl;
    }
    if (i == 0) rowptr[Nn] = Ee;
}

__global__ void fill_k(const int* __restrict__ ei, int* __restrict__ cursor,
                       int* __restrict__ col) {
    int e = blockIdx.x * blockDim.x + threadIdx.x;
    if (e >= Ee) return;
    int d = ei[Ee + e];
    int p = atomicAdd(&cursor[d], 1);
    col[p] = ei[e];
}

// ---------------- pooling (sum + count fused) / head ------------------------------
#define PR 16
__global__ void pool_k(const float* __restrict__ h, const int* __restrict__ batch,
                       float* __restrict__ pool, float* __restrict__ cnt) {
    int gw = (blockIdx.x * blockDim.x + threadIdx.x) >> 5;
    int lane = threadIdx.x & 31;
    const int NB = (Nn + PR - 1) / PR;
    if (gw >= NB) return;
    int n0 = gw * PR;
    int n1 = n0 + PR < Nn ? n0 + PR : Nn;
    float4 acc = make_float4(0.f, 0.f, 0.f, 0.f);
    float cacc = 0.f;
    int cur = batch[n0];
    for (int n = n0; n < n1; n++) {
        int g = batch[n];
        if (g != cur) {
            red4(&pool[(size_t)cur * Hh + lane * 4], acc);
            if (lane == 0) atomicAdd(&cnt[cur], cacc);
            acc = make_float4(0.f, 0.f, 0.f, 0.f);
            cacc = 0.f;
            cur = g;
        }
        float4 v = *reinterpret_cast<const float4*>(h + (size_t)n * Hh + lane * 4);
        acc.x += v.x; acc.y += v.y; acc.z += v.z; acc.w += v.w;
        cacc += 1.f;
    }
    red4(&pool[(size_t)cur * Hh + lane * 4], acc);
    if (lane == 0) atomicAdd(&cnt[cur], cacc);
}

__global__ void out_k(const float* __restrict__ g2, const float* __restrict__ ow,
                      const float* __restrict__ ob, float* __restrict__ out) {
    int g = blockIdx.x * blockDim.x + threadIdx.x;
    if (g >= Gg) return;
    float s0 = ob[0], s1 = ob[1];
#pragma unroll 4
    for (int k = 0; k < Hh; k++) {
        float v = g2[g * Hh + k];
        s0 += v * ow[k * 2 + 0];
        s1 += v * ow[k * 2 + 1];
    }
    out[g * 2 + 0] = s0;
    out[g * 2 + 1] = s1;
}

// ---------------- launch ----------------------------------------------------------
extern "C" void kernel_launch(void* const* d_in, const int* in_sizes, int n_in,
                              void* d_out, int out_size) {
    const float* x     = (const float*)d_in[0];
    const int*   ei    = (const int*)  d_in[1];
    const int*   batch = (const int*)  d_in[2];
    const float* b1[3], *b2[3], *b3[3];
    WP wp;
    for (int L = 0; L < 3; L++) {
        wp.p[3 * L + 0] = (const float*)d_in[3 + 6 * L + 0];
        b1[L]           = (const float*)d_in[3 + 6 * L + 1];
        wp.p[3 * L + 1] = (const float*)d_in[3 + 6 * L + 2];
        b2[L]           = (const float*)d_in[3 + 6 * L + 3];
        wp.p[3 * L + 2] = (const float*)d_in[3 + 6 * L + 4];
        b3[L]           = (const float*)d_in[3 + 6 * L + 5];
    }
    wp.p[9]  = (const float*)d_in[21];
    const float* fc0b = (const float*)d_in[22];
    wp.p[10] = (const float*)d_in[23];
    const float* fc1b = (const float*)d_in[24];
    const float* outw = (const float*)d_in[25];
    const float* outb = (const float*)d_in[26];

    float *hA, *hB, *pool, *cnt, *hd2;
    int *deg, *rowptr, *colv, *bsum;
    __nv_bfloat16 *wth, *wtl;
    cudaGetSymbolAddress((void**)&hA,     g_hA);
    cudaGetSymbolAddress((void**)&hB,     g_hB);
    cudaGetSymbolAddress((void**)&pool,   g_pool);
    cudaGetSymbolAddress((void**)&cnt,    g_cnt);
    cudaGetSymbolAddress((void**)&hd2,    g_hd2);
    cudaGetSymbolAddress((void**)&deg,    g_deg);
    cudaGetSymbolAddress((void**)&rowptr, g_rowptr);
    cudaGetSymbolAddress((void**)&colv,   g_col);
    cudaGetSymbolAddress((void**)&bsum,   g_bsum);
    cudaGetSymbolAddress((void**)&wth,    g_wth);
    cudaGetSymbolAddress((void**)&wtl,    g_wtl);

    auto woff = [](int s) -> size_t { return s == 0 ? 0 : (size_t)4096 + (size_t)(s - 1) * 16384; };

    cudaFuncSetAttribute(fused_mlp<FIN, 3, 1, 0>, cudaFuncAttributeMaxDynamicSharedMemorySize, SMEM_FUSED);
    cudaFuncSetAttribute(fused_mlp<Hh, 3, 1, 0>,  cudaFuncAttributeMaxDynamicSharedMemorySize, SMEM_FUSED);
    cudaFuncSetAttribute(fused_mlp<Hh, 3, 1, 1>,  cudaFuncAttributeMaxDynamicSharedMemorySize, SMEM_FUSED);
    cudaFuncSetAttribute(fused_mlp<Hh, 2, 2, 0>,  cudaFuncAttributeMaxDynamicSharedMemorySize, SMEM_FUSED);

    const int TB = 256;
    int ggrid = (Nn + 63) / 64;   // 2344
    int hgrid = (Gg + 63) / 64;   // 32

    // ---- weight prep + deg zero (one launch) + CSR build ----
    prep_all<<<PREP_WBLOCKS + PREP_ZBLOCKS, 128>>>(wp, wth, wtl, deg);
    deg_k<<<(Ee + TB - 1) / TB, TB>>>(ei, deg);
    scan1<<<NB_SCAN, 256>>>(deg, bsum);
    scan2<<<1, 1024>>>(bsum);
    scan3<<<NB_SCAN, 256>>>(deg, bsum, rowptr, deg);
    fill_k<<<(Ee + TB - 1) / TB, TB>>>(ei, deg, colv);

    // ---- layer 0: gather(x) + MLP -> hA ----
    {
        FusedW fw;
        for (int s = 0; s < 3; s++) { fw.wh[s] = wth + woff(s); fw.wl[s] = wtl + woff(s); }
        fw.b[0] = b1[0]; fw.b[1] = b2[0]; fw.b[2] = b3[0];
        fused_mlp<FIN, 3, 1, 0><<<ggrid, 256, SMEM_FUSED>>>(x, rowptr, colv, nullptr, fw, hA,
                                                            nullptr, nullptr, Nn);
    }
    // ---- layer 1: gather(hA) + MLP -> hB ----
    {
        FusedW fw;
        for (int s = 0; s < 3; s++) { fw.wh[s] = wth + woff(3 + s); fw.wl[s] = wtl + woff(3 + s); }
        fw.b[0] = b1[1]; fw.b[1] = b2[1]; fw.b[2] = b3[1];
        fused_mlp<Hh, 3, 1, 0><<<ggrid, 256, SMEM_FUSED>>>(hA, rowptr, colv, nullptr, fw, hB,
                                                           nullptr, nullptr, Nn);
    }
    // ---- layer 2: gather(hB) + MLP -> hA (zeroes pool + cnt inline) ----
    {
        FusedW fw;
        for (int s = 0; s < 3; s++) { fw.wh[s] = wth + woff(6 + s); fw.wl[s] = wtl + woff(6 + s); }
        fw.b[0] = b1[2]; fw.b[1] = b2[2]; fw.b[2] = b3[2];
        fused_mlp<Hh, 3, 1, 1><<<ggrid, 256, SMEM_FUSED>>>(hB, rowptr, colv, nullptr, fw, hA,
                                                           pool, cnt, Nn);
    }

    // ---- global mean pool (sum + count in one kernel) ----
    {
        int warps = (Nn + PR - 1) / PR;
        pool_k<<<(warps * 32 + TB - 1) / TB, TB>>>(hA, batch, pool, cnt);
    }

    // ---- classifier head (fc0 + fc1 fused; /count folded into A-load) ----
    {
        FusedW fw;
        fw.wh[0] = wth + woff(9);  fw.wl[0] = wtl + woff(9);
        fw.wh[1] = wth + woff(10); fw.wl[1] = wtl + woff(10);
        fw.wh[2] = nullptr;        fw.wl[2] = nullptr;
        fw.b[0] = fc0b; fw.b[1] = fc1b; fw.b[2] = nullptr;
        fused_mlp<Hh, 2, 2, 0><<<hgrid, 256, SMEM_FUSED>>>(pool, nullptr, nullptr, cnt, fw, hd2,
                                                           nullptr, nullptr, Gg);
    }
    out_k<<<(Gg + 127) / 128, 128>>>(hd2, outw, outb, (float*)d_out);
}

// round 13
// speedup vs baseline: 1.0569x; 1.0156x over previous
#include <cuda_runtime.h>
#include <cuda_bf16.h>
#include <cstdint>

#define Nn  150000
#define Ee  600000
#define FIN 32
#define Hh  128
#define Gg  2048
#define NB_SCAN 586   // ceil(Nn/256)

// ---------------- scratch (device globals) ----------------------------------
__device__ float g_hA [Nn * Hh];
__device__ float g_hB [Nn * Hh];
__device__ float g_pool[Gg * Hh];
__device__ float g_cnt [Gg];
__device__ float g_hd2 [Gg * Hh];
__device__ int   g_deg [Nn];        // also used as fill cursor
__device__ int   g_rowptr[Nn + 1];
__device__ int   g_col [Ee];
__device__ int   g_bsum[1024];
#define WTOT (4096 + 10 * 16384)
__device__ __align__(256) __nv_bfloat16 g_wth[WTOT];
__device__ __align__(256) __nv_bfloat16 g_wtl[WTOT];

// ---------------- helpers -----------------------------------------------------
__device__ __forceinline__ uint32_t smem_u32(const void* p) {
    uint32_t a;
    asm("{ .reg .u64 t; cvta.to.shared.u64 t, %1; cvt.u32.u64 %0, t; }" : "=r"(a) : "l"(p));
    return a;
}

__device__ __forceinline__ void ldsm4(uint32_t (&r)[4], uint32_t addr) {
    asm volatile("ldmatrix.sync.aligned.m8n8.x4.shared.b16 {%0,%1,%2,%3}, [%4];"
                 : "=r"(r[0]), "=r"(r[1]), "=r"(r[2]), "=r"(r[3]) : "r"(addr));
}

__device__ __forceinline__ void mma16816(float (&c)[4], const uint32_t (&a)[4],
                                         uint32_t b0, uint32_t b1) {
    asm volatile(
        "mma.sync.aligned.m16n8k16.row.col.f32.bf16.bf16.f32 "
        "{%0,%1,%2,%3},{%4,%5,%6,%7},{%8,%9},{%0,%1,%2,%3};"
        : "+f"(c[0]), "+f"(c[1]), "+f"(c[2]), "+f"(c[3])
        : "r"(a[0]), "r"(a[1]), "r"(a[2]), "r"(a[3]), "r"(b0), "r"(b1));
}

__device__ __forceinline__ void split2(float a, float b, uint32_t& hv, uint32_t& lv) {
    __nv_bfloat16 ha = __float2bfloat16(a), hb = __float2bfloat16(b);
    float la = a - __bfloat162float(ha), lb = b - __bfloat162float(hb);
    __nv_bfloat162 hp = __halves2bfloat162(ha, hb);
    __nv_bfloat162 lp = __floats2bfloat162_rn(la, lb);
    hv = *reinterpret_cast<uint32_t*>(&hp);
    lv = *reinterpret_cast<uint32_t*>(&lp);
}

__device__ __forceinline__ void red4(float* p, float4 v) {
    asm volatile("red.global.add.v4.f32 [%0], {%1, %2, %3, %4};"
                 :: "l"(p), "f"(v.x), "f"(v.y), "f"(v.z), "f"(v.w) : "memory");
}

// ---------------- smem layout (round-5 proven config) ---------------------------
#define PITCH 136
#define OFF_A_HI 0u
#define OFF_A_LO 17408u
#define OFF_B_HI 34816u
#define OFF_B_LO 69632u
#define SMEM_FUSED 104448

template<int Ks>
__device__ __forceinline__ void gemm_acc(uint32_t sb, float (&acc)[2][4][4],
                                         int lane, int warp_m, int warp_n) {
#pragma unroll
    for (int i = 0; i < 2; i++)
#pragma unroll
        for (int j = 0; j < 4; j++)
#pragma unroll
            for (int k = 0; k < 4; k++) acc[i][j][k] = 0.f;

    int a_r = lane & 15;
    int a_c = (lane & 16) ? 8 : 0;
    int b_r = (lane & 7) + ((lane & 16) ? 8 : 0);
    int b_c = (lane & 8) ? 8 : 0;

#pragma unroll
    for (int kk = 0; kk < Ks / 16; kk++) {
        uint32_t ah[2][4], al[2][4], bh[2][4], bl[2][4];
#pragma unroll
        for (int mt = 0; mt < 2; mt++) {
            uint32_t off = (uint32_t)(((warp_m * 32 + mt * 16 + a_r) * PITCH + kk * 16 + a_c) * 2);
            ldsm4(ah[mt], sb + OFF_A_HI + off);
            ldsm4(al[mt], sb + OFF_A_LO + off);
        }
#pragma unroll
        for (int p = 0; p < 2; p++) {
            uint32_t off = (uint32_t)(((warp_n * 32 + p * 16 + b_r) * PITCH + kk * 16 + b_c) * 2);
            ldsm4(bh[p], sb + OFF_B_HI + off);
            ldsm4(bl[p], sb + OFF_B_LO + off);
        }
#pragma unroll
        for (int mt = 0; mt < 2; mt++)
#pragma unroll
            for (int nt = 0; nt < 4; nt++) {
                int p = nt >> 1, q = (nt & 1) * 2;
                mma16816(acc[mt][nt], ah[mt], bh[p][q], bh[p][q + 1]);
                mma16816(acc[mt][nt], ah[mt], bl[p][q], bl[p][q + 1]);
                mma16816(acc[mt][nt], al[mt], bh[p][q], bh[p][q + 1]);
            }
    }
}

__device__ __forceinline__ void stage_to_smem(char* smem, float (&acc)[2][4][4],
                                              const float* __restrict__ bias,
                                              int lane, int warp_m, int warp_n) {
    int qrow = lane >> 2, qcol = (lane & 3) * 2;
#pragma unroll
    for (int mt = 0; mt < 2; mt++) {
        int r0 = warp_m * 32 + mt * 16 + qrow;
#pragma unroll
        for (int nt = 0; nt < 4; nt++) {
            int col = warp_n * 32 + nt * 8 + qcol;
            float bs0 = __ldg(bias + col), bs1 = __ldg(bias + col + 1);
            float o0 = fmaxf(acc[mt][nt][0] + bs0, 0.f);
            float o1 = fmaxf(acc[mt][nt][1] + bs1, 0.f);
            float o2 = fmaxf(acc[mt][nt][2] + bs0, 0.f);
            float o3 = fmaxf(acc[mt][nt][3] + bs1, 0.f);
            uint32_t h0, l0, h1, l1;
            split2(o0, o1, h0, l0);
            split2(o2, o3, h1, l1);
            *reinterpret_cast<uint32_t*>(smem + OFF_A_HI + ((size_t)r0 * PITCH + col) * 2) = h0;
            *reinterpret_cast<uint32_t*>(smem + OFF_A_LO + ((size_t)r0 * PITCH + col) * 2) = l0;
            *reinterpret_cast<uint32_t*>(smem + OFF_A_HI + ((size_t)(r0 + 8) * PITCH + col) * 2) = h1;
            *reinterpret_cast<uint32_t*>(smem + OFF_A_LO + ((size_t)(r0 + 8) * PITCH + col) * 2) = l1;
        }
    }
}

template<int Kw>
__device__ __forceinline__ void load_w(char* smem, const __nv_bfloat16* __restrict__ wh,
                                       const __nv_bfloat16* __restrict__ wl, int tid) {
    constexpr int CH = Kw / 8;
    constexpr int ITER = 128 * CH / 256;
#pragma unroll
    for (int it = 0; it < ITER; it++) {
        int l = tid + it * 256;
        int row = l / CH, col = (l % CH) * 8;
        *reinterpret_cast<uint4*>(smem + OFF_B_HI + ((size_t)row * PITCH + col) * 2) =
            *reinterpret_cast<const uint4*>(wh + (size_t)row * Kw + col);
        *reinterpret_cast<uint4*>(smem + OFF_B_LO + ((size_t)row * PITCH + col) * 2) =
            *reinterpret_cast<const uint4*>(wl + (size_t)row * Kw + col);
    }
}

struct FusedW {
    const __nv_bfloat16* wh[3];
    const __nv_bfloat16* wl[3];
    const float* b[3];
};

// ---------------- fused gather + MLP ---------------------------------------------
// GATHER: 0 = plain load; 1 = CSR gather(sum A[col]) + self (serial loop); 2 = load / max(cnt,1).
// EPI: 0 = write C; 1 = write C + zero pool/cnt inline; 2 = pool-reduce epilogue (no C).
template<int K0, int NST, int GATHER, int EPI>
__global__ __launch_bounds__(256, 2)
void fused_mlp(const float* __restrict__ A,
               const int* __restrict__ rowptr, const int* __restrict__ colv,
               const float* __restrict__ cntp, const int* __restrict__ batch,
               FusedW fw, float* __restrict__ C,
               float* __restrict__ Z, float* __restrict__ Zc, int M) {
    extern __shared__ char smem[];
    uint32_t sb = smem_u32(smem);
    int tid = threadIdx.x, lane = tid & 31, wid = tid >> 5;
    int warp_m = wid & 1, warp_n = wid >> 1;
    int m0 = blockIdx.x * 64;

    // ---- stage A tile (64 x K0) ----
    if (GATHER == 0 || GATHER == 2) {
        constexpr int CH = K0 / 4;
        constexpr int ITER = 64 * CH / 256;
#pragma unroll
        for (int it = 0; it < ITER; it++) {
            int l = tid + it * 256;
            int row = l / CH, col = (l % CH) * 4;
            float4 v = make_float4(0.f, 0.f, 0.f, 0.f);
            int m = m0 + row;
            if (m < M) {
                v = *reinterpret_cast<const float4*>(A + (size_t)m * K0 + col);
                if (GATHER == 2) {
                    float inv = 1.f / fmaxf(__ldg(cntp + m), 1.f);
                    v.x *= inv; v.y *= inv; v.z *= inv; v.w *= inv;
                }
            }
            uint32_t h0, l0, h1, l1;
            split2(v.x, v.y, h0, l0);
            split2(v.z, v.w, h1, l1);
            *reinterpret_cast<uint2*>(smem + OFF_A_HI + ((size_t)row * PITCH + col) * 2) = make_uint2(h0, h1);
            *reinterpret_cast<uint2*>(smem + OFF_A_LO + ((size_t)row * PITCH + col) * 2) = make_uint2(l0, l1);
        }
    } else if (K0 == 128) {
        // warp = 8 consecutive rows; lane = 4-feature chunk (serial neighbor loop)
#pragma unroll
        for (int i = 0; i < 8; i++) {
            int lrow = wid * 8 + i;
            int row = m0 + lrow;
            float4 acc = make_float4(0.f, 0.f, 0.f, 0.f);
            if (row < M) {
                acc = *reinterpret_cast<const float4*>(A + (size_t)row * 128 + lane * 4);
                int beg = rowptr[row], end = rowptr[row + 1];
                for (int j = beg; j < end; j++) {
                    int s = colv[j];
                    float4 v = *reinterpret_cast<const float4*>(A + (size_t)s * 128 + lane * 4);
                    acc.x += v.x; acc.y += v.y; acc.z += v.z; acc.w += v.w;
                }
            }
            uint32_t h0, l0, h1, l1;
            split2(acc.x, acc.y, h0, l0);
            split2(acc.z, acc.w, h1, l1);
            *reinterpret_cast<uint2*>(smem + OFF_A_HI + ((size_t)lrow * PITCH + lane * 4) * 2) = make_uint2(h0, h1);
            *reinterpret_cast<uint2*>(smem + OFF_A_LO + ((size_t)lrow * PITCH + lane * 4) * 2) = make_uint2(l0, l1);
        }
    } else {
        // K0 == 32: warp covers 4 rows at a time (serial neighbor loop)
        int sub = lane >> 3, c = (lane & 7) * 4;
#pragma unroll
        for (int i = 0; i < 2; i++) {
            int lrow = wid * 8 + i * 4 + sub;
            int row = m0 + lrow;
            float4 acc = make_float4(0.f, 0.f, 0.f, 0.f);
            if (row < M) {
                acc = *reinterpret_cast<const float4*>(A + (size_t)row * FIN + c);
                int beg = rowptr[row], end = rowptr[row + 1];
                for (int j = beg; j < end; j++) {
                    int s = colv[j];
                    float4 v = *reinterpret_cast<const float4*>(A + (size_t)s * FIN + c);
                    acc.x += v.x; acc.y += v.y; acc.z += v.z; acc.w += v.w;
                }
            }
            uint32_t h0, l0, h1, l1;
            split2(acc.x, acc.y, h0, l0);
            split2(acc.z, acc.w, h1, l1);
            *reinterpret_cast<uint2*>(smem + OFF_A_HI + ((size_t)lrow * PITCH + c) * 2) = make_uint2(h0, h1);
            *reinterpret_cast<uint2*>(smem + OFF_A_LO + ((size_t)lrow * PITCH + c) * 2) = make_uint2(l0, l1);
        }
    }
    load_w<K0>(smem, fw.wh[0], fw.wl[0], tid);
    __syncthreads();

    if (EPI == 1) {
        const float4 z4 = make_float4(0.f, 0.f, 0.f, 0.f);
        if (blockIdx.x < 32) {                        // pool: 2048 rows = 32 blocks x 64 rows
#pragma unroll
            for (int it = 0; it < 8; it++) {
                int i = tid + it * 256;
                int row = (int)blockIdx.x * 64 + (i >> 5);
                reinterpret_cast<float4*>(Z + (size_t)row * 128)[i & 31] = z4;
            }
        } else if (blockIdx.x == 32) {                // cnt: 2048 floats
#pragma unroll
            for (int it = 0; it < 2; it++)
                reinterpret_cast<float4*>(Zc)[tid + it * 256] = z4;
        }
    }

    float acc[2][4][4];
    gemm_acc<K0>(sb, acc, lane, warp_m, warp_n);

#pragma unroll
    for (int s = 1; s < NST; s++) {
        __syncthreads();
        stage_to_smem(smem, acc, fw.b[s - 1], lane, warp_m, warp_n);
        load_w<128>(smem, fw.wh[s], fw.wl[s], tid);
        __syncthreads();
        gemm_acc<128>(sb, acc, lane, warp_m, warp_n);
    }

    const float* bias = fw.b[NST - 1];
    int qrow = lane >> 2, qcol = (lane & 3) * 2;

    if (EPI == 2) {
        // ---- pooled epilogue: stage fp32 rows to smem, run-length red4 to pool ----
        __syncthreads();                               // all warps done reading smem tiles
        float* srow = reinterpret_cast<float*>(smem);  // 64 rows x 128 floats = 32KB
#pragma unroll
        for (int mt = 0; mt < 2; mt++) {
            int r0 = warp_m * 32 + mt * 16 + qrow;
#pragma unroll
            for (int nt = 0; nt < 4; nt++) {
                int col = warp_n * 32 + nt * 8 + qcol;
                float bs0 = __ldg(bias + col), bs1 = __ldg(bias + col + 1);
                srow[(size_t)r0 * 128 + col]           = fmaxf(acc[mt][nt][0] + bs0, 0.f);
                srow[(size_t)r0 * 128 + col + 1]       = fmaxf(acc[mt][nt][1] + bs1, 0.f);
                srow[(size_t)(r0 + 8) * 128 + col]     = fmaxf(acc[mt][nt][2] + bs0, 0.f);
                srow[(size_t)(r0 + 8) * 128 + col + 1] = fmaxf(acc[mt][nt][3] + bs1, 0.f);
            }
        }
        __syncthreads();
        // warp wid owns rows [wid*8, wid*8+8); lane covers feature chunk lane*4
        int base = wid * 8;
        float4 a4 = make_float4(0.f, 0.f, 0.f, 0.f);
        float cacc = 0.f;
        int cur = -1;
#pragma unroll
        for (int i = 0; i < 8; i++) {
            int row = m0 + base + i;
            if (row >= M) break;
            int g = __ldg(batch + row);
            if (g != cur) {
                if (cur >= 0) {
                    red4(&Z[(size_t)cur * 128 + lane * 4], a4);
                    if (lane == 0) atomicAdd(&Zc[cur], cacc);
                }
                cur = g; a4 = make_float4(0.f, 0.f, 0.f, 0.f); cacc = 0.f;
            }
            float4 v = *reinterpret_cast<const float4*>(&srow[(size_t)(base + i) * 128 + lane * 4]);
            a4.x += v.x; a4.y += v.y; a4.z += v.z; a4.w += v.w;
            cacc += 1.f;
        }
        if (cur >= 0) {
            red4(&Z[(size_t)cur * 128 + lane * 4], a4);
            if (lane == 0) atomicAdd(&Zc[cur], cacc);
        }
        return;
    }

    // ---- standard epilogue: relu(acc+bias) -> fp32 global ----
#pragma unroll
    for (int mt = 0; mt < 2; mt++) {
        int r0 = m0 + warp_m * 32 + mt * 16 + qrow;
        int r1 = r0 + 8;
#pragma unroll
        for (int nt = 0; nt < 4; nt++) {
            int col = warp_n * 32 + nt * 8 + qcol;
            float bs0 = __ldg(bias + col), bs1 = __ldg(bias + col + 1);
            float o0 = fmaxf(acc[mt][nt][0] + bs0, 0.f);
            float o1 = fmaxf(acc[mt][nt][1] + bs1, 0.f);
            float o2 = fmaxf(acc[mt][nt][2] + bs0, 0.f);
            float o3 = fmaxf(acc[mt][nt][3] + bs1, 0.f);
            if (r0 < M) *reinterpret_cast<float2*>(C + (size_t)r0 * 128 + col) = make_float2(o0, o1);
            if (r1 < M) *reinterpret_cast<float2*>(C + (size_t)r1 * 128 + col) = make_float2(o2, o3);
        }
    }
}

// ---------------- weight prep (11 slots) + deg zero, one launch -----------------
struct WP { const float* p[11]; };
#define PREP_WBLOCKS (11 * 128)
#define PREP_ZBLOCKS ((Nn + 127) / 128)

__global__ void prep_all(WP wp, __nv_bfloat16* __restrict__ hi, __nv_bfloat16* __restrict__ lo,
                         int* __restrict__ deg) {
    if (blockIdx.x >= PREP_WBLOCKS) {
        int i = (blockIdx.x - PREP_WBLOCKS) * 128 + threadIdx.x;
        if (i < Nn) deg[i] = 0;
        return;
    }
    int slot = blockIdx.x >> 7;
    int n = blockIdx.x & 127;
    int K = (slot == 0) ? FIN : Hh;
    size_t off = (slot == 0) ? 0 : (size_t)4096 + (size_t)(slot - 1) * 16384;
    const float* W = wp.p[slot];
    for (int k = threadIdx.x; k < K; k += blockDim.x) {
        float v = W[k * Hh + n];
        __nv_bfloat16 h = __float2bfloat16(v);
        hi[off + (size_t)n * K + k] = h;
        lo[off + (size_t)n * K + k] = __float2bfloat16(v - __bfloat162float(h));
    }
}

// ---------------- CSR build -----------------------------------------------------
__global__ void deg_k(const int* __restrict__ ei, int* __restrict__ deg) {
    int e = blockIdx.x * blockDim.x + threadIdx.x;
    if (e < Ee) atomicAdd(&deg[ei[Ee + e]], 1);
}

__global__ void scan1(const int* __restrict__ deg, int* __restrict__ bsum) {
    __shared__ int sm[256];
    int i = blockIdx.x * 256 + threadIdx.x;
    sm[threadIdx.x] = (i < Nn) ? deg[i] : 0;
    __syncthreads();
    for (int s = 128; s > 0; s >>= 1) {
        if (threadIdx.x < s) sm[threadIdx.x] += sm[threadIdx.x + s];
        __syncthreads();
    }
    if (threadIdx.x == 0) bsum[blockIdx.x] = sm[0];
}

__global__ void scan2(int* __restrict__ bsum) {
    __shared__ int sm[1024];
    int t = threadIdx.x;
    sm[t] = (t < NB_SCAN) ? bsum[t] : 0;
    __syncthreads();
    for (int s = 1; s < 1024; s <<= 1) {
        int v = (t >= s) ? sm[t - s] : 0;
        __syncthreads();
        sm[t] += v;
        __syncthreads();
    }
    if (t < NB_SCAN) bsum[t] = sm[t];   // inclusive per-block sums
}

__global__ void scan3(const int* __restrict__ deg, const int* __restrict__ bsum,
                      int* __restrict__ rowptr, int* __restrict__ cursor) {
    __shared__ int sm[256];
    int i = blockIdx.x * 256 + threadIdx.x;
    int v = (i < Nn) ? deg[i] : 0;
    sm[threadIdx.x] = v;
    __syncthreads();
    for (int s = 1; s < 256; s <<= 1) {
        int u = (threadIdx.x >= s) ? sm[threadIdx.x - s] : 0;
        __syncthreads();
        sm[threadIdx.x] += u;
        __syncthreads();
    }
    int excl = sm[threadIdx.x] - v;
    int base = (blockIdx.x > 0) ? bsum[blockIdx.x - 1] : 0;
    if (i < Nn) {
        rowptr[i] = base + excl;
        cursor[i] = base + excl;
    }
    if (i == 0) rowptr[Nn] = Ee;
}

__global__ void fill_k(const int* __restrict__ ei, int* __restrict__ cursor,
                       int* __restrict__ col) {
    int e = blockIdx.x * blockDim.x + threadIdx.x;
    if (e >= Ee) return;
    int d = ei[Ee + e];
    int p = atomicAdd(&cursor[d], 1);
    col[p] = ei[e];
}

// ---------------- output head ------------------------------------------------------
__global__ void out_k(const float* __restrict__ g2, const float* __restrict__ ow,
                      const float* __restrict__ ob, float* __restrict__ out) {
    int g = blockIdx.x * blockDim.x + threadIdx.x;
    if (g >= Gg) return;
    float s0 = ob[0], s1 = ob[1];
#pragma unroll 4
    for (int k = 0; k < Hh; k++) {
        float v = g2[g * Hh + k];
        s0 += v * ow[k * 2 + 0];
        s1 += v * ow[k * 2 + 1];
    }
    out[g * 2 + 0] = s0;
    out[g * 2 + 1] = s1;
}

// ---------------- launch ----------------------------------------------------------
extern "C" void kernel_launch(void* const* d_in, const int* in_sizes, int n_in,
                              void* d_out, int out_size) {
    const float* x     = (const float*)d_in[0];
    const int*   ei    = (const int*)  d_in[1];
    const int*   batch = (const int*)  d_in[2];
    const float* b1[3], *b2[3], *b3[3];
    WP wp;
    for (int L = 0; L < 3; L++) {
        wp.p[3 * L + 0] = (const float*)d_in[3 + 6 * L + 0];
        b1[L]           = (const float*)d_in[3 + 6 * L + 1];
        wp.p[3 * L + 1] = (const float*)d_in[3 + 6 * L + 2];
        b2[L]           = (const float*)d_in[3 + 6 * L + 3];
        wp.p[3 * L + 2] = (const float*)d_in[3 + 6 * L + 4];
        b3[L]           = (const float*)d_in[3 + 6 * L + 5];
    }
    wp.p[9]  = (const float*)d_in[21];
    const float* fc0b = (const float*)d_in[22];
    wp.p[10] = (const float*)d_in[23];
    const float* fc1b = (const float*)d_in[24];
    const float* outw = (const float*)d_in[25];
    const float* outb = (const float*)d_in[26];

    float *hA, *hB, *pool, *cnt, *hd2;
    int *deg, *rowptr, *colv, *bsum;
    __nv_bfloat16 *wth, *wtl;
    cudaGetSymbolAddress((void**)&hA,     g_hA);
    cudaGetSymbolAddress((void**)&hB,     g_hB);
    cudaGetSymbolAddress((void**)&pool,   g_pool);
    cudaGetSymbolAddress((void**)&cnt,    g_cnt);
    cudaGetSymbolAddress((void**)&hd2,    g_hd2);
    cudaGetSymbolAddress((void**)&deg,    g_deg);
    cudaGetSymbolAddress((void**)&rowptr, g_rowptr);
    cudaGetSymbolAddress((void**)&colv,   g_col);
    cudaGetSymbolAddress((void**)&bsum,   g_bsum);
    cudaGetSymbolAddress((void**)&wth,    g_wth);
    cudaGetSymbolAddress((void**)&wtl,    g_wtl);

    auto woff = [](int s) -> size_t { return s == 0 ? 0 : (size_t)4096 + (size_t)(s - 1) * 16384; };

    cudaFuncSetAttribute(fused_mlp<FIN, 3, 1, 0>, cudaFuncAttributeMaxDynamicSharedMemorySize, SMEM_FUSED);
    cudaFuncSetAttribute(fused_mlp<Hh, 3, 1, 1>,  cudaFuncAttributeMaxDynamicSharedMemorySize, SMEM_FUSED);
    cudaFuncSetAttribute(fused_mlp<Hh, 3, 1, 2>,  cudaFuncAttributeMaxDynamicSharedMemorySize, SMEM_FUSED);
    cudaFuncSetAttribute(fused_mlp<Hh, 2, 2, 0>,  cudaFuncAttributeMaxDynamicSharedMemorySize, SMEM_FUSED);

    const int TB = 256;
    int ggrid = (Nn + 63) / 64;   // 2344
    int hgrid = (Gg + 63) / 64;   // 32

    // ---- weight prep + deg zero (one launch) + CSR build ----
    prep_all<<<PREP_WBLOCKS + PREP_ZBLOCKS, 128>>>(wp, wth, wtl, deg);
    deg_k<<<(Ee + TB - 1) / TB, TB>>>(ei, deg);
    scan1<<<NB_SCAN, 256>>>(deg, bsum);
    scan2<<<1, 1024>>>(bsum);
    scan3<<<NB_SCAN, 256>>>(deg, bsum, rowptr, deg);
    fill_k<<<(Ee + TB - 1) / TB, TB>>>(ei, deg, colv);

    // ---- layer 0: gather(x) + MLP -> hA ----
    {
        FusedW fw;
        for (int s = 0; s < 3; s++) { fw.wh[s] = wth + woff(s); fw.wl[s] = wtl + woff(s); }
        fw.b[0] = b1[0]; fw.b[1] = b2[0]; fw.b[2] = b3[0];
        fused_mlp<FIN, 3, 1, 0><<<ggrid, 256, SMEM_FUSED>>>(x, rowptr, colv, nullptr, nullptr,
                                                            fw, hA, nullptr, nullptr, Nn);
    }
    // ---- layer 1: gather(hA) + MLP -> hB (zeroes pool + cnt inline) ----
    {
        FusedW fw;
        for (int s = 0; s < 3; s++) { fw.wh[s] = wth + woff(3 + s); fw.wl[s] = wtl + woff(3 + s); }
        fw.b[0] = b1[1]; fw.b[1] = b2[1]; fw.b[2] = b3[1];
        fused_mlp<Hh, 3, 1, 1><<<ggrid, 256, SMEM_FUSED>>>(hA, rowptr, colv, nullptr, nullptr,
                                                           fw, hB, pool, cnt, Nn);
    }
    // ---- layer 2: gather(hB) + MLP -> pooled directly (no h write, no pool_k) ----
    {
        FusedW fw;
        for (int s = 0; s < 3; s++) { fw.wh[s] = wth + woff(6 + s); fw.wl[s] = wtl + woff(6 + s); }
        fw.b[0] = b1[2]; fw.b[1] = b2[2]; fw.b[2] = b3[2];
        fused_mlp<Hh, 3, 1, 2><<<ggrid, 256, SMEM_FUSED>>>(hB, rowptr, colv, nullptr, batch,
                                                           fw, nullptr, pool, cnt, Nn);
    }

    // ---- classifier head (fc0 + fc1 fused; /count folded into A-load) ----
    {
        FusedW fw;
        fw.wh[0] = wth + woff(9);  fw.wl[0] = wtl + woff(9);
        fw.wh[1] = wth + woff(10); fw.wl[1] = wtl + woff(10);
        fw.wh[2] = nullptr;        fw.wl[2] = nullptr;
        fw.b[0] = fc0b; fw.b[1] = fc1b; fw.b[2] = nullptr;
        fused_mlp<Hh, 2, 2, 0><<<hgrid, 256, SMEM_FUSED>>>(pool, nullptr, nullptr, cnt, nullptr,
                                                           fw, hd2, nullptr, nullptr, Gg);
    }
    out_k<<<(Gg + 127) / 128, 128>>>(hd2, outw, outb, (float*)d_out);
}

// round 14
// speedup vs baseline: 1.0886x; 1.0300x over previous
#include <cuda_runtime.h>
#include <cuda_bf16.h>
#include <cstdint>

#define Nn  150000
#define Ee  600000
#define FIN 32
#define Hh  128
#define Gg  2048
#define NB_SCAN 586   // ceil(Nn/256)

// ---------------- scratch (device globals) ----------------------------------
__device__ float g_hA [Nn * Hh];
__device__ float g_hB [Nn * Hh];
__device__ float g_pool[Gg * Hh];
__device__ float g_cnt [Gg];
__device__ int   g_deg [Nn];        // also used as fill cursor
__device__ int   g_rowptr[Nn + 1];
__device__ int   g_col [Ee];
__device__ int   g_bsum[1024];
#define WTOT (4096 + 10 * 16384)
__device__ __align__(256) __nv_bfloat16 g_wth[WTOT];
__device__ __align__(256) __nv_bfloat16 g_wtl[WTOT];

// ---------------- helpers -----------------------------------------------------
__device__ __forceinline__ uint32_t smem_u32(const void* p) {
    uint32_t a;
    asm("{ .reg .u64 t; cvta.to.shared.u64 t, %1; cvt.u32.u64 %0, t; }" : "=r"(a) : "l"(p));
    return a;
}

__device__ __forceinline__ void ldsm4(uint32_t (&r)[4], uint32_t addr) {
    asm volatile("ldmatrix.sync.aligned.m8n8.x4.shared.b16 {%0,%1,%2,%3}, [%4];"
                 : "=r"(r[0]), "=r"(r[1]), "=r"(r[2]), "=r"(r[3]) : "r"(addr));
}

__device__ __forceinline__ void mma16816(float (&c)[4], const uint32_t (&a)[4],
                                         uint32_t b0, uint32_t b1) {
    asm volatile(
        "mma.sync.aligned.m16n8k16.row.col.f32.bf16.bf16.f32 "
        "{%0,%1,%2,%3},{%4,%5,%6,%7},{%8,%9},{%0,%1,%2,%3};"
        : "+f"(c[0]), "+f"(c[1]), "+f"(c[2]), "+f"(c[3])
        : "r"(a[0]), "r"(a[1]), "r"(a[2]), "r"(a[3]), "r"(b0), "r"(b1));
}

__device__ __forceinline__ void split2(float a, float b, uint32_t& hv, uint32_t& lv) {
    __nv_bfloat16 ha = __float2bfloat16(a), hb = __float2bfloat16(b);
    float la = a - __bfloat162float(ha), lb = b - __bfloat162float(hb);
    __nv_bfloat162 hp = __halves2bfloat162(ha, hb);
    __nv_bfloat162 lp = __floats2bfloat162_rn(la, lb);
    hv = *reinterpret_cast<uint32_t*>(&hp);
    lv = *reinterpret_cast<uint32_t*>(&lp);
}

__device__ __forceinline__ void red4(float* p, float4 v) {
    asm volatile("red.global.add.v4.f32 [%0], {%1, %2, %3, %4};"
                 :: "l"(p), "f"(v.x), "f"(v.y), "f"(v.z), "f"(v.w) : "memory");
}

// ---------------- smem layout (round-5 proven config) ---------------------------
#define PITCH 136
#define OFF_A_HI 0u
#define OFF_A_LO 17408u
#define OFF_B_HI 34816u
#define OFF_B_LO 69632u
#define SMEM_FUSED 104448

template<int Ks>
__device__ __forceinline__ void gemm_acc(uint32_t sb, float (&acc)[2][4][4],
                                         int lane, int warp_m, int warp_n) {
#pragma unroll
    for (int i = 0; i < 2; i++)
#pragma unroll
        for (int j = 0; j < 4; j++)
#pragma unroll
            for (int k = 0; k < 4; k++) acc[i][j][k] = 0.f;

    int a_r = lane & 15;
    int a_c = (lane & 16) ? 8 : 0;
    int b_r = (lane & 7) + ((lane & 16) ? 8 : 0);
    int b_c = (lane & 8) ? 8 : 0;

#pragma unroll
    for (int kk = 0; kk < Ks / 16; kk++) {
        uint32_t ah[2][4], al[2][4], bh[2][4], bl[2][4];
#pragma unroll
        for (int mt = 0; mt < 2; mt++) {
            uint32_t off = (uint32_t)(((warp_m * 32 + mt * 16 + a_r) * PITCH + kk * 16 + a_c) * 2);
            ldsm4(ah[mt], sb + OFF_A_HI + off);
            ldsm4(al[mt], sb + OFF_A_LO + off);
        }
#pragma unroll
        for (int p = 0; p < 2; p++) {
            uint32_t off = (uint32_t)(((warp_n * 32 + p * 16 + b_r) * PITCH + kk * 16 + b_c) * 2);
            ldsm4(bh[p], sb + OFF_B_HI + off);
            ldsm4(bl[p], sb + OFF_B_LO + off);
        }
#pragma unroll
        for (int mt = 0; mt < 2; mt++)
#pragma unroll
            for (int nt = 0; nt < 4; nt++) {
                int p = nt >> 1, q = (nt & 1) * 2;
                mma16816(acc[mt][nt], ah[mt], bh[p][q], bh[p][q + 1]);
                mma16816(acc[mt][nt], ah[mt], bl[p][q], bl[p][q + 1]);
                mma16816(acc[mt][nt], al[mt], bh[p][q], bh[p][q + 1]);
            }
    }
}

__device__ __forceinline__ void stage_to_smem(char* smem, float (&acc)[2][4][4],
                                              const float* __restrict__ bias,
                                              int lane, int warp_m, int warp_n) {
    int qrow = lane >> 2, qcol = (lane & 3) * 2;
#pragma unroll
    for (int mt = 0; mt < 2; mt++) {
        int r0 = warp_m * 32 + mt * 16 + qrow;
#pragma unroll
        for (int nt = 0; nt < 4; nt++) {
            int col = warp_n * 32 + nt * 8 + qcol;
            float bs0 = __ldg(bias + col), bs1 = __ldg(bias + col + 1);
            float o0 = fmaxf(acc[mt][nt][0] + bs0, 0.f);
            float o1 = fmaxf(acc[mt][nt][1] + bs1, 0.f);
            float o2 = fmaxf(acc[mt][nt][2] + bs0, 0.f);
            float o3 = fmaxf(acc[mt][nt][3] + bs1, 0.f);
            uint32_t h0, l0, h1, l1;
            split2(o0, o1, h0, l0);
            split2(o2, o3, h1, l1);
            *reinterpret_cast<uint32_t*>(smem + OFF_A_HI + ((size_t)r0 * PITCH + col) * 2) = h0;
            *reinterpret_cast<uint32_t*>(smem + OFF_A_LO + ((size_t)r0 * PITCH + col) * 2) = l0;
            *reinterpret_cast<uint32_t*>(smem + OFF_A_HI + ((size_t)(r0 + 8) * PITCH + col) * 2) = h1;
            *reinterpret_cast<uint32_t*>(smem + OFF_A_LO + ((size_t)(r0 + 8) * PITCH + col) * 2) = l1;
        }
    }
}

template<int Kw>
__device__ __forceinline__ void load_w(char* smem, const __nv_bfloat16* __restrict__ wh,
                                       const __nv_bfloat16* __restrict__ wl, int tid) {
    constexpr int CH = Kw / 8;
    constexpr int ITER = 128 * CH / 256;
#pragma unroll
    for (int it = 0; it < ITER; it++) {
        int l = tid + it * 256;
        int row = l / CH, col = (l % CH) * 8;
        *reinterpret_cast<uint4*>(smem + OFF_B_HI + ((size_t)row * PITCH + col) * 2) =
            *reinterpret_cast<const uint4*>(wh + (size_t)row * Kw + col);
        *reinterpret_cast<uint4*>(smem + OFF_B_LO + ((size_t)row * PITCH + col) * 2) =
            *reinterpret_cast<const uint4*>(wl + (size_t)row * Kw + col);
    }
}

struct FusedW {
    const __nv_bfloat16* wh[3];
    const __nv_bfloat16* wl[3];
    const float* b[3];
};

// ---------------- fused gather + MLP ---------------------------------------------
// GATHER: 0 = plain load; 1 = CSR gather + self (serial loop); 2 = load / max(cnt,1).
// EPI: 0 = write C; 1 = write C + zero pool/cnt; 2 = pool-reduce; 3 = out-head dot.
template<int K0, int NST, int GATHER, int EPI>
__global__ __launch_bounds__(256, 2)
void fused_mlp(const float* __restrict__ A,
               const int* __restrict__ rowptr, const int* __restrict__ colv,
               const float* __restrict__ cntp, const int* __restrict__ batch,
               FusedW fw, float* __restrict__ C,
               float* __restrict__ Z, float* __restrict__ Zc,
               const float* __restrict__ ow, const float* __restrict__ ob,
               float* __restrict__ outp, int M) {
    extern __shared__ char smem[];
    uint32_t sb = smem_u32(smem);
    int tid = threadIdx.x, lane = tid & 31, wid = tid >> 5;
    int warp_m = wid & 1, warp_n = wid >> 1;
    int m0 = blockIdx.x * 64;

    // ---- stage A tile (64 x K0) ----
    if (GATHER == 0 || GATHER == 2) {
        constexpr int CH = K0 / 4;
        constexpr int ITER = 64 * CH / 256;
#pragma unroll
        for (int it = 0; it < ITER; it++) {
            int l = tid + it * 256;
            int row = l / CH, col = (l % CH) * 4;
            float4 v = make_float4(0.f, 0.f, 0.f, 0.f);
            int m = m0 + row;
            if (m < M) {
                v = *reinterpret_cast<const float4*>(A + (size_t)m * K0 + col);
                if (GATHER == 2) {
                    float inv = 1.f / fmaxf(__ldg(cntp + m), 1.f);
                    v.x *= inv; v.y *= inv; v.z *= inv; v.w *= inv;
                }
            }
            uint32_t h0, l0, h1, l1;
            split2(v.x, v.y, h0, l0);
            split2(v.z, v.w, h1, l1);
            *reinterpret_cast<uint2*>(smem + OFF_A_HI + ((size_t)row * PITCH + col) * 2) = make_uint2(h0, h1);
            *reinterpret_cast<uint2*>(smem + OFF_A_LO + ((size_t)row * PITCH + col) * 2) = make_uint2(l0, l1);
        }
    } else if (K0 == 128) {
        // warp = 8 consecutive rows; lane = 4-feature chunk (serial neighbor loop)
#pragma unroll
        for (int i = 0; i < 8; i++) {
            int lrow = wid * 8 + i;
            int row = m0 + lrow;
            float4 acc = make_float4(0.f, 0.f, 0.f, 0.f);
            if (row < M) {
                acc = *reinterpret_cast<const float4*>(A + (size_t)row * 128 + lane * 4);
                int beg = rowptr[row], end = rowptr[row + 1];
                for (int j = beg; j < end; j++) {
                    int s = colv[j];
                    float4 v = *reinterpret_cast<const float4*>(A + (size_t)s * 128 + lane * 4);
                    acc.x += v.x; acc.y += v.y; acc.z += v.z; acc.w += v.w;
                }
            }
            uint32_t h0, l0, h1, l1;
            split2(acc.x, acc.y, h0, l0);
            split2(acc.z, acc.w, h1, l1);
            *reinterpret_cast<uint2*>(smem + OFF_A_HI + ((size_t)lrow * PITCH + lane * 4) * 2) = make_uint2(h0, h1);
            *reinterpret_cast<uint2*>(smem + OFF_A_LO + ((size_t)lrow * PITCH + lane * 4) * 2) = make_uint2(l0, l1);
        }
    } else {
        // K0 == 32: warp covers 4 rows at a time (serial neighbor loop)
        int sub = lane >> 3, c = (lane & 7) * 4;
#pragma unroll
        for (int i = 0; i < 2; i++) {
            int lrow = wid * 8 + i * 4 + sub;
            int row = m0 + lrow;
            float4 acc = make_float4(0.f, 0.f, 0.f, 0.f);
            if (row < M) {
                acc = *reinterpret_cast<const float4*>(A + (size_t)row * FIN + c);
                int beg = rowptr[row], end = rowptr[row + 1];
                for (int j = beg; j < end; j++) {
                    int s = colv[j];
                    float4 v = *reinterpret_cast<const float4*>(A + (size_t)s * FIN + c);
                    acc.x += v.x; acc.y += v.y; acc.z += v.z; acc.w += v.w;
                }
            }
            uint32_t h0, l0, h1, l1;
            split2(acc.x, acc.y, h0, l0);
            split2(acc.z, acc.w, h1, l1);
            *reinterpret_cast<uint2*>(smem + OFF_A_HI + ((size_t)lrow * PITCH + c) * 2) = make_uint2(h0, h1);
            *reinterpret_cast<uint2*>(smem + OFF_A_LO + ((size_t)lrow * PITCH + c) * 2) = make_uint2(l0, l1);
        }
    }
    load_w<K0>(smem, fw.wh[0], fw.wl[0], tid);
    __syncthreads();

    if (EPI == 1) {
        const float4 z4 = make_float4(0.f, 0.f, 0.f, 0.f);
        if (blockIdx.x < 32) {                        // pool: 2048 rows = 32 blocks x 64 rows
#pragma unroll
            for (int it = 0; it < 8; it++) {
                int i = tid + it * 256;
                int row = (int)blockIdx.x * 64 + (i >> 5);
                reinterpret_cast<float4*>(Z + (size_t)row * 128)[i & 31] = z4;
            }
        } else if (blockIdx.x == 32) {                // cnt: 2048 floats
#pragma unroll
            for (int it = 0; it < 2; it++)
                reinterpret_cast<float4*>(Zc)[tid + it * 256] = z4;
        }
    }

    float acc[2][4][4];
    gemm_acc<K0>(sb, acc, lane, warp_m, warp_n);

#pragma unroll
    for (int s = 1; s < NST; s++) {
        __syncthreads();
        stage_to_smem(smem, acc, fw.b[s - 1], lane, warp_m, warp_n);
        load_w<128>(smem, fw.wh[s], fw.wl[s], tid);
        __syncthreads();
        gemm_acc<128>(sb, acc, lane, warp_m, warp_n);
    }

    const float* bias = fw.b[NST - 1];
    int qrow = lane >> 2, qcol = (lane & 3) * 2;

    if (EPI == 2 || EPI == 3) {
        // ---- smem-staged epilogue: fp32 rows into freed A region ----
        __syncthreads();
        float* srow = reinterpret_cast<float*>(smem);  // 64 rows x 128 floats = 32KB
#pragma unroll
        for (int mt = 0; mt < 2; mt++) {
            int r0 = warp_m * 32 + mt * 16 + qrow;
#pragma unroll
            for (int nt = 0; nt < 4; nt++) {
                int col = warp_n * 32 + nt * 8 + qcol;
                float bs0 = __ldg(bias + col), bs1 = __ldg(bias + col + 1);
                srow[(size_t)r0 * 128 + col]           = fmaxf(acc[mt][nt][0] + bs0, 0.f);
                srow[(size_t)r0 * 128 + col + 1]       = fmaxf(acc[mt][nt][1] + bs1, 0.f);
                srow[(size_t)(r0 + 8) * 128 + col]     = fmaxf(acc[mt][nt][2] + bs0, 0.f);
                srow[(size_t)(r0 + 8) * 128 + col + 1] = fmaxf(acc[mt][nt][3] + bs1, 0.f);
            }
        }
        __syncthreads();
        int base = wid * 8;

        if (EPI == 2) {
            // run-length pooled reduction over sorted batch
            float4 a4 = make_float4(0.f, 0.f, 0.f, 0.f);
            float cacc = 0.f;
            int cur = -1;
#pragma unroll
            for (int i = 0; i < 8; i++) {
                int row = m0 + base + i;
                if (row >= M) break;
                int g = __ldg(batch + row);
                if (g != cur) {
                    if (cur >= 0) {
                        red4(&Z[(size_t)cur * 128 + lane * 4], a4);
                        if (lane == 0) atomicAdd(&Zc[cur], cacc);
                    }
                    cur = g; a4 = make_float4(0.f, 0.f, 0.f, 0.f); cacc = 0.f;
                }
                float4 v = *reinterpret_cast<const float4*>(&srow[(size_t)(base + i) * 128 + lane * 4]);
                a4.x += v.x; a4.y += v.y; a4.z += v.z; a4.w += v.w;
                cacc += 1.f;
            }
            if (cur >= 0) {
                red4(&Z[(size_t)cur * 128 + lane * 4], a4);
                if (lane == 0) atomicAdd(&Zc[cur], cacc);
            }
        } else {
            // EPI == 3: out = srow @ ow + ob, 2 outputs per row
            float4 q0 = *reinterpret_cast<const float4*>(ow + lane * 8);
            float4 q1 = *reinterpret_cast<const float4*>(ow + lane * 8 + 4);
#pragma unroll
            for (int i = 0; i < 8; i++) {
                int row = m0 + base + i;
                if (row >= M) break;
                float4 v = *reinterpret_cast<const float4*>(&srow[(size_t)(base + i) * 128 + lane * 4]);
                float s0 = v.x * q0.x + v.y * q0.z + v.z * q1.x + v.w * q1.z;
                float s1 = v.x * q0.y + v.y * q0.w + v.z * q1.y + v.w * q1.w;
#pragma unroll
                for (int d = 16; d > 0; d >>= 1) {
                    s0 += __shfl_xor_sync(0xffffffff, s0, d);
                    s1 += __shfl_xor_sync(0xffffffff, s1, d);
                }
                if (lane == 0)
                    *reinterpret_cast<float2*>(outp + (size_t)row * 2) =
                        make_float2(s0 + __ldg(ob), s1 + __ldg(ob + 1));
            }
        }
        return;
    }

    // ---- standard epilogue: relu(acc+bias) -> fp32 global ----
#pragma unroll
    for (int mt = 0; mt < 2; mt++) {
        int r0 = m0 + warp_m * 32 + mt * 16 + qrow;
        int r1 = r0 + 8;
#pragma unroll
        for (int nt = 0; nt < 4; nt++) {
            int col = warp_n * 32 + nt * 8 + qcol;
            float bs0 = __ldg(bias + col), bs1 = __ldg(bias + col + 1);
            float o0 = fmaxf(acc[mt][nt][0] + bs0, 0.f);
            float o1 = fmaxf(acc[mt][nt][1] + bs1, 0.f);
            float o2 = fmaxf(acc[mt][nt][2] + bs0, 0.f);
            float o3 = fmaxf(acc[mt][nt][3] + bs1, 0.f);
            if (r0 < M) *reinterpret_cast<float2*>(C + (size_t)r0 * 128 + col) = make_float2(o0, o1);
            if (r1 < M) *reinterpret_cast<float2*>(C + (size_t)r1 * 128 + col) = make_float2(o2, o3);
        }
    }
}

// ---------------- weight prep (11 slots) + deg zero, one launch -----------------
struct WP { const float* p[11]; };
#define PREP_WBLOCKS (11 * 128)
#define PREP_ZBLOCKS ((Nn + 127) / 128)

__global__ void prep_all(WP wp, __nv_bfloat16* __restrict__ hi, __nv_bfloat16* __restrict__ lo,
                         int* __restrict__ deg) {
    if (blockIdx.x >= PREP_WBLOCKS) {
        int i = (blockIdx.x - PREP_WBLOCKS) * 128 + threadIdx.x;
        if (i < Nn) deg[i] = 0;
        return;
    }
    int slot = blockIdx.x >> 7;
    int n = blockIdx.x & 127;
    int K = (slot == 0) ? FIN : Hh;
    size_t off = (slot == 0) ? 0 : (size_t)4096 + (size_t)(slot - 1) * 16384;
    const float* W = wp.p[slot];
    for (int k = threadIdx.x; k < K; k += blockDim.x) {
        float v = W[k * Hh + n];
        __nv_bfloat16 h = __float2bfloat16(v);
        hi[off + (size_t)n * K + k] = h;
        lo[off + (size_t)n * K + k] = __float2bfloat16(v - __bfloat162float(h));
    }
}

// ---------------- CSR build -----------------------------------------------------
__global__ void deg_k(const int* __restrict__ ei, int* __restrict__ deg) {
    int e = blockIdx.x * blockDim.x + threadIdx.x;
    if (e < Ee) atomicAdd(&deg[ei[Ee + e]], 1);
}

// per-block sums only (raw, not scanned)
__global__ void scan1(const int* __restrict__ deg, int* __restrict__ bsum) {
    __shared__ int sm[256];
    int i = blockIdx.x * 256 + threadIdx.x;
    sm[threadIdx.x] = (i < Nn) ? deg[i] : 0;
    __syncthreads();
    for (int s = 128; s > 0; s >>= 1) {
        if (threadIdx.x < s) sm[threadIdx.x] += sm[threadIdx.x + s];
        __syncthreads();
    }
    if (threadIdx.x == 0) bsum[blockIdx.x] = sm[0];
}

// local scan + self-computed base from raw bsum (scan2 eliminated)
__global__ void scan3(const int* __restrict__ deg, const int* __restrict__ bsum,
                      int* __restrict__ rowptr, int* __restrict__ cursor) {
    __shared__ int sm[256];
    __shared__ int sbase;
    int t = threadIdx.x;
    // base = sum of bsum[0 .. blockIdx.x)
    int part = 0;
    for (int j = t; j < (int)blockIdx.x; j += 256) part += bsum[j];
    sm[t] = part;
    __syncthreads();
    for (int s = 128; s > 0; s >>= 1) {
        if (t < s) sm[t] += sm[t + s];
        __syncthreads();
    }
    if (t == 0) sbase = sm[0];
    __syncthreads();
    int base = sbase;
    __syncthreads();
    // local inclusive scan of this block's degrees
    int i = blockIdx.x * 256 + t;
    int v = (i < Nn) ? deg[i] : 0;
    sm[t] = v;
    __syncthreads();
    for (int s = 1; s < 256; s <<= 1) {
        int u = (t >= s) ? sm[t - s] : 0;
        __syncthreads();
        sm[t] += u;
        __syncthreads();
    }
    int excl = sm[t] - v;
    if (i < Nn) {
        rowptr[i] = base + excl;
        cursor[i] = base + excl;
    }
    if (i == 0) rowptr[Nn] = Ee;
}

__global__ void fill_k(const int* __restrict__ ei, int* __restrict__ cursor,
                       int* __restrict__ col) {
    int e = blockIdx.x * blockDim.x + threadIdx.x;
    if (e >= Ee) return;
    int d = ei[Ee + e];
    int p = atomicAdd(&cursor[d], 1);
    col[p] = ei[e];
}

// ---------------- launch ----------------------------------------------------------
extern "C" void kernel_launch(void* const* d_in, const int* in_sizes, int n_in,
                              void* d_out, int out_size) {
    const float* x     = (const float*)d_in[0];
    const int*   ei    = (const int*)  d_in[1];
    const int*   batch = (const int*)  d_in[2];
    const float* b1[3], *b2[3], *b3[3];
    WP wp;
    for (int L = 0; L < 3; L++) {
        wp.p[3 * L + 0] = (const float*)d_in[3 + 6 * L + 0];
        b1[L]           = (const float*)d_in[3 + 6 * L + 1];
        wp.p[3 * L + 1] = (const float*)d_in[3 + 6 * L + 2];
        b2[L]           = (const float*)d_in[3 + 6 * L + 3];
        wp.p[3 * L + 2] = (const float*)d_in[3 + 6 * L + 4];
        b3[L]           = (const float*)d_in[3 + 6 * L + 5];
    }
    wp.p[9]  = (const float*)d_in[21];
    const float* fc0b = (const float*)d_in[22];
    wp.p[10] = (const float*)d_in[23];
    const float* fc1b = (const float*)d_in[24];
    const float* outw = (const float*)d_in[25];
    const float* outb = (const float*)d_in[26];

    float *hA, *hB, *pool, *cnt;
    int *deg, *rowptr, *colv, *bsum;
    __nv_bfloat16 *wth, *wtl;
    cudaGetSymbolAddress((void**)&hA,     g_hA);
    cudaGetSymbolAddress((void**)&hB,     g_hB);
    cudaGetSymbolAddress((void**)&pool,   g_pool);
    cudaGetSymbolAddress((void**)&cnt,    g_cnt);
    cudaGetSymbolAddress((void**)&deg,    g_deg);
    cudaGetSymbolAddress((void**)&rowptr, g_rowptr);
    cudaGetSymbolAddress((void**)&colv,   g_col);
    cudaGetSymbolAddress((void**)&bsum,   g_bsum);
    cudaGetSymbolAddress((void**)&wth,    g_wth);
    cudaGetSymbolAddress((void**)&wtl,    g_wtl);

    auto woff = [](int s) -> size_t { return s == 0 ? 0 : (size_t)4096 + (size_t)(s - 1) * 16384; };

    cudaFuncSetAttribute(fused_mlp<FIN, 3, 1, 0>, cudaFuncAttributeMaxDynamicSharedMemorySize, SMEM_FUSED);
    cudaFuncSetAttribute(fused_mlp<Hh, 3, 1, 1>,  cudaFuncAttributeMaxDynamicSharedMemorySize, SMEM_FUSED);
    cudaFuncSetAttribute(fused_mlp<Hh, 3, 1, 2>,  cudaFuncAttributeMaxDynamicSharedMemorySize, SMEM_FUSED);
    cudaFuncSetAttribute(fused_mlp<Hh, 2, 2, 3>,  cudaFuncAttributeMaxDynamicSharedMemorySize, SMEM_FUSED);

    const int TB = 256;
    int ggrid = (Nn + 63) / 64;   // 2344
    int hgrid = (Gg + 63) / 64;   // 32

    // ---- weight prep + deg zero (one launch) + CSR build (scan2 eliminated) ----
    prep_all<<<PREP_WBLOCKS + PREP_ZBLOCKS, 128>>>(wp, wth, wtl, deg);
    deg_k<<<(Ee + TB - 1) / TB, TB>>>(ei, deg);
    scan1<<<NB_SCAN, 256>>>(deg, bsum);
    scan3<<<NB_SCAN, 256>>>(deg, bsum, rowptr, deg);
    fill_k<<<(Ee + TB - 1) / TB, TB>>>(ei, deg, colv);

    // ---- layer 0: gather(x) + MLP -> hA ----
    {
        FusedW fw;
        for (int s = 0; s < 3; s++) { fw.wh[s] = wth + woff(s); fw.wl[s] = wtl + woff(s); }
        fw.b[0] = b1[0]; fw.b[1] = b2[0]; fw.b[2] = b3[0];
        fused_mlp<FIN, 3, 1, 0><<<ggrid, 256, SMEM_FUSED>>>(x, rowptr, colv, nullptr, nullptr,
                                                            fw, hA, nullptr, nullptr,
                                                            nullptr, nullptr, nullptr, Nn);
    }
    // ---- layer 1: gather(hA) + MLP -> hB (zeroes pool + cnt inline) ----
    {
        FusedW fw;
        for (int s = 0; s < 3; s++) { fw.wh[s] = wth + woff(3 + s); fw.wl[s] = wtl + woff(3 + s); }
        fw.b[0] = b1[1]; fw.b[1] = b2[1]; fw.b[2] = b3[1];
        fused_mlp<Hh, 3, 1, 1><<<ggrid, 256, SMEM_FUSED>>>(hA, rowptr, colv, nullptr, nullptr,
                                                           fw, hB, pool, cnt,
                                                           nullptr, nullptr, nullptr, Nn);
    }
    // ---- layer 2: gather(hB) + MLP -> pooled directly ----
    {
        FusedW fw;
        for (int s = 0; s < 3; s++) { fw.wh[s] = wth + woff(6 + s); fw.wl[s] = wtl + woff(6 + s); }
        fw.b[0] = b1[2]; fw.b[1] = b2[2]; fw.b[2] = b3[2];
        fused_mlp<Hh, 3, 1, 2><<<ggrid, 256, SMEM_FUSED>>>(hB, rowptr, colv, nullptr, batch,
                                                           fw, nullptr, pool, cnt,
                                                           nullptr, nullptr, nullptr, Nn);
    }

    // ---- classifier head (fc0 + fc1 + output layer fused; /count in A-load) ----
    {
        FusedW fw;
        fw.wh[0] = wth + woff(9);  fw.wl[0] = wtl + woff(9);
        fw.wh[1] = wth + woff(10); fw.wl[1] = wtl + woff(10);
        fw.wh[2] = nullptr;        fw.wl[2] = nullptr;
        fw.b[0] = fc0b; fw.b[1] = fc1b; fw.b[2] = nullptr;
        fused_mlp<Hh, 2, 2, 3><<<hgrid, 256, SMEM_FUSED>>>(pool, nullptr, nullptr, cnt, nullptr,
                                                           fw, nullptr, nullptr, nullptr,
                                                           outw, outb, (float*)d_out, Gg);
    }
}